// round 11
// baseline (speedup 1.0000x reference)
#include <cuda_runtime.h>
#include <cstdint>
#include <math.h>

constexpr int kT = 4, kB = 8, kC = 384, kN = 1024;
constexpr float kEPS = 1e-5f;
constexpr int kW = kC * kC;                   // 147456
constexpr size_t kSP = (size_t)kT * kB * kC * kN;

// ---------------- device scratch ----------------
__device__ int8_t g_w8[14 * kW];    // q:0-3, k:4-7, v:8-11 (4 splits each), proj:12-13
__device__ int8_t g_sx[kSP];        // input spikes [t][b][n][c]
__device__ int8_t g_qb[kSP];        // q spikes     [t][b][n][c]
__device__ int8_t g_kb[kSP];        // k spikes     [t][b][c][n]
__device__ int8_t g_vb[kSP];        // v spikes     [t][b][c][n]
__device__ float   g_kvsum[kT * kB * kC];
__device__ uint8_t g_kvm[kT * kB * kC];   // kv spike mask bytes (0xFF / 0x00)

// split scales (exact powers of two)
__device__ __constant__ float c_SC[4] = {1.f/256.f, 1.f/32768.f, 1.f/4194304.f, 1.f/536870912.f};

// ---------------- helpers ----------------
__device__ __forceinline__ uint32_t smem_u32(const void* p) {
    uint32_t a;
    asm("{ .reg .u64 t; cvta.to.shared.u64 t, %1; cvt.u32.u64 %0, t; }" : "=r"(a) : "l"(p));
    return a;
}
__device__ __forceinline__ void cp16(uint32_t dst, const void* src) {
    asm volatile("cp.async.cg.shared.global [%0], [%1], 16;" :: "r"(dst), "l"(src));
}
__device__ __forceinline__ void ldm_x4(uint32_t* r, uint32_t addr) {
    asm volatile("ldmatrix.sync.aligned.m8n8.x4.shared.b16 {%0,%1,%2,%3}, [%4];"
                 : "=r"(r[0]), "=r"(r[1]), "=r"(r[2]), "=r"(r[3]) : "r"(addr));
}
__device__ __forceinline__ void imma16832(int* c, const uint32_t* a, uint32_t b0, uint32_t b1) {
    asm volatile("mma.sync.aligned.m16n8k32.row.col.s32.s8.s8.s32 "
                 "{%0,%1,%2,%3}, {%4,%5,%6,%7}, {%8,%9}, {%0,%1,%2,%3};"
                 : "+r"(c[0]), "+r"(c[1]), "+r"(c[2]), "+r"(c[3])
                 : "r"(a[0]), "r"(a[1]), "r"(a[2]), "r"(a[3]), "r"(b0), "r"(b1));
}

// fused-kernel smem layout (bytes)
constexpr int FA_ST   = 128 * 48;                 // one A stage: 128 rows x 48B pitch = 6144
constexpr int FB_OFF  = 2 * FA_ST;                // 12288
constexpr int FB_ST   = 64 * 400;                 // one B buffer: 64 rows x 400B pitch = 25600
constexpr int FSTG_OFF = FB_OFF + 2 * FB_ST;      // 63488 (spike staging)
// staging pitches MUST be multiples of 16 bytes (uint4 copy-out)
constexpr int QSP = 144;                          // q: 64 rows x 144B  = 9216
constexpr int KSP8 = 80;                          // kv: 128 rows x 80B = 10240
constexpr int FVSM_OFF = FSTG_OFF + 10240;        // 73728
constexpr int FSMEM    = FVSM_OFF + 256 * 32 * 4; // 106496

// proj smem
constexpr int PJA_ST  = 2 * 128 * 48;             // 2 splits = 12288
constexpr int PJB_OFF = PJA_ST;
constexpr int PJ_STAGE = PJA_ST + 64 * 48;        // 15360
constexpr int PJSMEM  = 2 * PJ_STAGE;             // 30720

// ---------------------------------------------------------------------------
// K0: fixed-point split of weights into s8 planes. q/k/v: 4 splits, proj: 2.
// ---------------------------------------------------------------------------
__global__ void split_w_kernel(const float* __restrict__ qw, const float* __restrict__ kw,
                               const float* __restrict__ vw, const float* __restrict__ pw) {
    int idx = blockIdx.x * 256 + threadIdx.x;
    if (idx >= 4 * kW) return;
    int mat = idx / kW;
    int e = idx - mat * kW;
    const float* src = (mat == 0) ? qw : (mat == 1) ? kw : (mat == 2) ? vw : pw;
    float r = src[e];
    const float SCL[4] = {256.f, 32768.f, 4194304.f, 536870912.f};
    int nsp = (mat < 3) ? 4 : 2;
    int base = (mat < 3) ? mat * 4 : 12;
#pragma unroll
    for (int s = 0; s < 4; s++) {
        if (s >= nsp) break;
        float a = rintf(r * SCL[s]);
        a = fminf(127.f, fmaxf(-127.f, a));
        g_w8[(size_t)(base + s) * kW + e] = (int8_t)a;
        r -= a / SCL[s];
    }
}

// ---------------------------------------------------------------------------
// K1: LIF on x [t][b][c][n] -> s8 spikes transposed to [t][b][n][c].
// ---------------------------------------------------------------------------
__global__ void lif_x_kernel(const float* __restrict__ x) {
    __shared__ int8_t sm[32][36];
    const int lane = threadIdx.x & 31, wid = threadIdx.x >> 5;
    const int n0 = blockIdx.x * 32, c0 = blockIdx.y * 32, b = blockIdx.z;
    float v[4] = {0.f, 0.f, 0.f, 0.f};
    for (int t = 0; t < kT; t++) {
#pragma unroll
        for (int j = 0; j < 4; j++) {
            int c = c0 + wid * 4 + j;
            float xv = x[((size_t)((t * kB + b) * kC + c)) * kN + n0 + lane];
            v[j] += (xv - v[j]) * 0.5f;
            int8_t s = 0;
            if (v[j] >= 0.5f) { s = 1; v[j] = 0.f; }
            sm[lane][wid * 4 + j] = s;
        }
        __syncthreads();
        int nr = wid * 4 + (lane >> 3);
        int cw = (lane & 7) * 4;
        uint32_t val = *(const uint32_t*)&sm[nr][cw];
        *(uint32_t*)&g_sx[((size_t)((t * kB + b) * kN + n0 + nr)) * kC + c0 + cw] = val;
        __syncthreads();
    }
}

// ---------------------------------------------------------------------------
// FUSED QKV: grid (16 ntiles, 9 = p*3+mtile, 8 b). Per t: 4 sequential s8
// split passes over K=384 (B tile smem-resident), IMMA s32 accumulation,
// exact fp32 merge, BN + LIF epilogue, spikes staged for coalesced stores.
// ---------------------------------------------------------------------------
__global__ __launch_bounds__(256, 2) void fused_qkv_kernel(
    const float* __restrict__ qg, const float* __restrict__ qbe, const float* __restrict__ qm, const float* __restrict__ qva,
    const float* __restrict__ kg, const float* __restrict__ kbe, const float* __restrict__ km, const float* __restrict__ kva,
    const float* __restrict__ vg, const float* __restrict__ vbe, const float* __restrict__ vm, const float* __restrict__ vva)
{
    extern __shared__ char dynsm[];
    const uint32_t shb = smem_u32(dynsm);
    float* vsm = (float*)(dynsm + FVSM_OFF);
    int8_t* stg = (int8_t*)(dynsm + FSTG_OFF);

    const int tid = threadIdx.x, wid = tid >> 5, lane = tid & 31;
    const int b = blockIdx.z;
    const int yy = blockIdx.y;
    const int p = (yy >= 6) ? 2 : ((yy >= 3) ? 1 : 0);
    const int mtile = yy - p * 3;
    const int m0 = mtile * 128, n0 = blockIdx.x * 64;
    const int pbase = p * 4;

    const int mw = wid >> 1, nw = wid & 1;     // warp: m32 x n32
    const int gr = lane >> 2, gc = (lane & 3) * 2;

    const float *G, *Be, *Mn, *Va;
    if (p == 0)      { G = qg; Be = qbe; Mn = qm; Va = qva; }
    else if (p == 1) { G = kg; Be = kbe; Mn = km; Va = kva; }
    else             { G = vg; Be = vbe; Mn = vm; Va = vva; }
    float scv[2][2], mnv[2][2], bev[2][2];
#pragma unroll
    for (int mi = 0; mi < 2; mi++)
#pragma unroll
        for (int half = 0; half < 2; half++) {
            int cc = m0 + mw * 32 + mi * 16 + half * 8 + gr;
            scv[mi][half] = G[cc] / sqrtf(Va[cc] + kEPS);
            mnv[mi][half] = Mn[cc];
            bev[mi][half] = Be[cc];
        }

#pragma unroll
    for (int j = 0; j < 32; j++) vsm[j * 256 + tid] = 0.f;

    // A chunk loader: global chunk index g (0..191): t=g/48, s=(g%48)/12, ck=g%12
    auto load_A = [&](int g) {
        const int s = (g % 48) / 12, ck = g % 12;
        const uint32_t dst = shb + (g & 1) * FA_ST;
        const int row = tid >> 1, half = tid & 1;
        cp16(dst + row * 48 + half * 16,
             g_w8 + (size_t)(pbase + s) * kW + (size_t)(m0 + row) * kC + ck * 32 + half * 16);
    };
    // B part loader: part in 0..2, 512 cp16 each
    auto load_B = [&](int t, int part) {
        const uint32_t dst = shb + FB_OFF + (t & 1) * FB_ST;
#pragma unroll
        for (int it = 0; it < 2; it++) {
            int i = part * 512 + it * 256 + tid;
            int row = i / 24, pp = i % 24;
            cp16(dst + row * 400 + pp * 16,
                 g_sx + ((size_t)((t * kB + b) * kN + n0 + row)) * kC + pp * 16);
        }
    };

    // prologue: B(t=0) full + A(0)
    load_B(0, 0); load_B(0, 1); load_B(0, 2);
    load_A(0);
    asm volatile("cp.async.commit_group;");

    float uacc[2][4][4];
    int acc[2][4][4];
#pragma unroll
    for (int mi = 0; mi < 2; mi++)
#pragma unroll
        for (int nj = 0; nj < 4; nj++)
#pragma unroll
            for (int q = 0; q < 4; q++) acc[mi][nj][q] = 0;

    for (int g = 0; g < 192; g++) {
        const int c48 = g % 48, t = g / 48;
        const int ck = c48 % 12, s = c48 / 12;
        if (g + 1 < 192) {
            load_A(g + 1);
            if (c48 >= 36 && c48 < 39 && t < 3) load_B(t + 1, c48 - 36);
            asm volatile("cp.async.commit_group;");
            asm volatile("cp.async.wait_group 1;");
        } else {
            asm volatile("cp.async.wait_group 0;");
        }
        __syncthreads();

        // B fragments (resident tile, pitch 400)
        const uint32_t Bb = shb + FB_OFF + (t & 1) * FB_ST;
        uint32_t bfr[2][4];
#pragma unroll
        for (int seg = 0; seg < 2; seg++) {
            int row = nw * 32 + seg * 16 + (lane & 7) + ((lane >> 4) & 1) * 8;
            int kb = ck * 32 + ((lane >> 3) & 1) * 16;
            ldm_x4(bfr[seg], Bb + row * 400 + kb);
        }
        // A fragments (chunk stage, pitch 48)
        const uint32_t Ab = shb + (g & 1) * FA_ST;
        uint32_t afr[2][4];
#pragma unroll
        for (int mi = 0; mi < 2; mi++) {
            int row = mw * 32 + mi * 16 + (lane & 15);
            ldm_x4(afr[mi], Ab + row * 48 + (lane >> 4) * 16);
        }
#pragma unroll
        for (int mi = 0; mi < 2; mi++)
#pragma unroll
            for (int nj = 0; nj < 4; nj++) {
                int seg = nj >> 1, odd = nj & 1;
                imma16832(acc[mi][nj], afr[mi], bfr[seg][odd * 2], bfr[seg][odd * 2 + 1]);
            }
        __syncthreads();

        if (ck == 11) {
            // merge split s into uacc (exact: |acc| < 2^16)
            const float sc = c_SC[s];
#pragma unroll
            for (int mi = 0; mi < 2; mi++)
#pragma unroll
                for (int nj = 0; nj < 4; nj++)
#pragma unroll
                    for (int q = 0; q < 4; q++) {
                        float f = (float)acc[mi][nj][q] * sc;
                        uacc[mi][nj][q] = (s == 0) ? f : uacc[mi][nj][q] + f;
                        acc[mi][nj][q] = 0;
                    }
            if (s == 3) {
                // ---- BN + LIF epilogue for timestep t ----
#pragma unroll
                for (int mi = 0; mi < 2; mi++)
#pragma unroll
                    for (int nj = 0; nj < 4; nj++)
#pragma unroll
                        for (int q = 0; q < 4; q++) {
                            const int half = q >> 1;
                            const int j = mi * 16 + nj * 4 + q;
                            float u = (uacc[mi][nj][q] - mnv[mi][half]) * scv[mi][half] + bev[mi][half];
                            float vv = vsm[j * 256 + tid];
                            vv += (u - vv) * 0.5f;
                            int8_t sp = 0;
                            if (vv >= 0.5f) { sp = 1; vv = 0.f; }
                            vsm[j * 256 + tid] = vv;
                            const int cl = mw * 32 + mi * 16 + half * 8 + gr;
                            const int n = nw * 32 + nj * 8 + gc + (q & 1);
                            if (p == 0) stg[n * QSP + cl] = sp;
                            else        stg[cl * KSP8 + n] = sp;
                        }
                __syncthreads();
                if (p == 0) {
                    // 64 n-rows x 128 bytes = 512 uint4
#pragma unroll
                    for (int it = 0; it < 2; it++) {
                        int i = it * 256 + tid;
                        int n = i >> 3, w = i & 7;
                        uint4 val = *(const uint4*)&stg[n * QSP + w * 16];
                        *(uint4*)&g_qb[((size_t)((t * kB + b) * kN + n0 + n)) * kC + m0 + w * 16] = val;
                    }
                } else {
                    int8_t* dstb = (p == 1) ? g_kb : g_vb;
                    // 128 c-rows x 64 bytes = 512 uint4
#pragma unroll
                    for (int it = 0; it < 2; it++) {
                        int i = it * 256 + tid;
                        int cl = i >> 2, w = i & 3;
                        uint4 val = *(const uint4*)&stg[cl * KSP8 + w * 16];
                        *(uint4*)&dstb[((size_t)((t * kB + b) * kC + m0 + cl)) * kN + n0 + w * 16] = val;
                    }
                }
                __syncthreads();
            }
        }
    }
}

// ---------------------------------------------------------------------------
// kvsum: one warp per (t,b,c) row: dp4a dot of binary s8 k,v (exact).
// ---------------------------------------------------------------------------
__global__ void kvsum_kernel() {
    const int row = blockIdx.x * 8 + (threadIdx.x >> 5);
    const int lane = threadIdx.x & 31;
    const int* kp = (const int*)(g_kb + (size_t)row * kN);
    const int* vp = (const int*)(g_vb + (size_t)row * kN);
    int s = 0;
#pragma unroll
    for (int i = lane; i < kN / 4; i += 32)
        s = __dp4a(kp[i], vp[i], s);
#pragma unroll
    for (int o = 16; o; o >>= 1) s += __shfl_xor_sync(0xffffffffu, s, o);
    if (lane == 0) g_kvsum[row] = (float)s;
}

// ---------------------------------------------------------------------------
// K4: talking heads + LIF on kv -> mask bytes (0xFF spike, 0x00 no spike).
// ---------------------------------------------------------------------------
__global__ void kv_kernel(const float* __restrict__ th_w) {
    __shared__ float th[64];
    if (threadIdx.x < 64) th[threadIdx.x] = th_w[threadIdx.x];
    __syncthreads();
    int d = threadIdx.x % 48;
    int b = threadIdx.x / 48;
    float v[8];
#pragma unroll
    for (int o = 0; o < 8; o++) v[o] = 0.0f;
#pragma unroll
    for (int t = 0; t < kT; t++) {
        float kvv[8];
#pragma unroll
        for (int h = 0; h < 8; h++)
            kvv[h] = g_kvsum[(t * kB + b) * kC + h * 48 + d];
#pragma unroll
        for (int o = 0; o < 8; o++) {
            float a = 0.0f;
#pragma unroll
            for (int h = 0; h < 8; h++) a += th[o * 8 + h] * kvv[h];
            v[o] += (a - v[o]) * 0.5f;
            uint8_t msk = 0;
            if (v[o] >= 0.5f) { msk = 0xFF; v[o] = 0.f; }
            g_kvm[(t * kB + b) * kC + o * 48 + d] = msk;
        }
    }
}

// ---------------------------------------------------------------------------
// PROJ GEMM: s8 2-split IMMA; kvs folded as byte-AND mask on B fragments.
// Epilogue: +bias, BN, +identity.
// ---------------------------------------------------------------------------
__global__ __launch_bounds__(256, 2) void gemm_proj_kernel(
    const float* __restrict__ pg, const float* __restrict__ pbe,
    const float* __restrict__ pm, const float* __restrict__ pva,
    const float* __restrict__ bias, const float* __restrict__ xres, float* __restrict__ outp)
{
    extern __shared__ char dynsm[];
    const uint32_t shb = smem_u32(dynsm);

    const int tid = threadIdx.x, wid = tid >> 5, lane = tid & 31;
    const int bz = blockIdx.z, t = bz >> 3, b = bz & 7;
    const int m0 = blockIdx.y * 128, n0 = blockIdx.x * 64;

    const int8_t* Bimg = g_qb + ((size_t)(t * kB + b) * kN) * kC;
    const uint32_t* kvm32 = (const uint32_t*)(g_kvm + (t * kB + b) * kC);

    const int mw = wid >> 1, nw = wid & 1;

    int acc[2][2][4][4];   // [split][mi][nj][q]
#pragma unroll
    for (int sp = 0; sp < 2; sp++)
#pragma unroll
        for (int mi = 0; mi < 2; mi++)
#pragma unroll
            for (int nj = 0; nj < 4; nj++)
#pragma unroll
                for (int q = 0; q < 4; q++) acc[sp][mi][nj][q] = 0;

    auto load_chunk = [&](int ck, int st) {
        const uint32_t sb = shb + st * PJ_STAGE;
#pragma unroll
        for (int it = 0; it < 2; it++) {
            int i = it * 256 + tid;
            int sp = i >> 8, rem = i & 255, row = rem >> 1, half = rem & 1;
            cp16(sb + sp * (128 * 48) + row * 48 + half * 16,
                 g_w8 + (size_t)(12 + sp) * kW + (size_t)(m0 + row) * kC + ck * 32 + half * 16);
        }
        if (tid < 128) {
            int row = tid >> 1, half = tid & 1;
            cp16(sb + PJB_OFF + row * 48 + half * 16,
                 Bimg + (size_t)(n0 + row) * kC + ck * 32 + half * 16);
        }
        asm volatile("cp.async.commit_group;");
    };

    load_chunk(0, 0);
    for (int ck = 0; ck < 12; ck++) {
        if (ck + 1 < 12) {
            load_chunk(ck + 1, (ck + 1) & 1);
            asm volatile("cp.async.wait_group 1;");
        } else {
            asm volatile("cp.async.wait_group 0;");
        }
        __syncthreads();
        const uint32_t sb = shb + (ck & 1) * PJ_STAGE;

        uint32_t bfr[2][4];
#pragma unroll
        for (int seg = 0; seg < 2; seg++) {
            int row = nw * 32 + seg * 16 + (lane & 7) + ((lane >> 4) & 1) * 8;
            int kb = ((lane >> 3) & 1) * 16;
            ldm_x4(bfr[seg], sb + PJB_OFF + row * 48 + kb);
        }
        // fold kvs: byte-AND mask per k position
        uint32_t mk0 = kvm32[ck * 8 + (lane & 3)];
        uint32_t mk1 = kvm32[ck * 8 + 4 + (lane & 3)];
#pragma unroll
        for (int seg = 0; seg < 2; seg++) {
            bfr[seg][0] &= mk0; bfr[seg][1] &= mk1;
            bfr[seg][2] &= mk0; bfr[seg][3] &= mk1;
        }
#pragma unroll
        for (int sp = 0; sp < 2; sp++) {
            uint32_t afr[2][4];
#pragma unroll
            for (int mi = 0; mi < 2; mi++) {
                int row = mw * 32 + mi * 16 + (lane & 15);
                ldm_x4(afr[mi], sb + sp * (128 * 48) + row * 48 + (lane >> 4) * 16);
            }
#pragma unroll
            for (int mi = 0; mi < 2; mi++)
#pragma unroll
                for (int nj = 0; nj < 4; nj++) {
                    int seg = nj >> 1, odd = nj & 1;
                    imma16832(acc[sp][mi][nj], afr[mi], bfr[seg][odd * 2], bfr[seg][odd * 2 + 1]);
                }
        }
        __syncthreads();
    }

    const int gr = lane >> 2, gc = (lane & 3) * 2;
    const size_t imgoff = ((size_t)(t * kB + b) * kC) * kN;
    const float S0 = 1.f / 256.f, S1 = 1.f / 32768.f;

#pragma unroll
    for (int mi = 0; mi < 2; mi++) {
#pragma unroll
        for (int half = 0; half < 2; half++) {
            const int c = m0 + mw * 32 + mi * 16 + gr + half * 8;
            const float sc = pg[c] / sqrtf(pva[c] + kEPS);
            const float mn = pm[c], be = pbe[c];
            const float bi = bias[c];
            size_t rowoff = imgoff + (size_t)c * kN;
            float* dst = outp + rowoff;
#pragma unroll
            for (int nj = 0; nj < 4; nj++) {
                const int n = n0 + nw * 32 + nj * 8 + gc;
                float v0 = (float)acc[0][mi][nj][half * 2 + 0] * S0 + (float)acc[1][mi][nj][half * 2 + 0] * S1;
                float v1 = (float)acc[0][mi][nj][half * 2 + 1] * S0 + (float)acc[1][mi][nj][half * 2 + 1] * S1;
                float2 xv = *(const float2*)(xres + rowoff + n);
                float2 o;
                o.x = ((v0 + bi) - mn) * sc + be + xv.x;
                o.y = ((v1 + bi) - mn) * sc + be + xv.y;
                *(float2*)(dst + n) = o;
            }
        }
    }
}

// ---------------------------------------------------------------------------
extern "C" void kernel_launch(void* const* d_in, const int* in_sizes, int n_in,
                              void* d_out, int out_size)
{
    const float* x   = (const float*)d_in[0];
    const float* qw  = (const float*)d_in[1];
    const float* kw  = (const float*)d_in[2];
    const float* vw  = (const float*)d_in[3];
    const float* thw = (const float*)d_in[4];
    const float* pw  = (const float*)d_in[5];
    const float* pb  = (const float*)d_in[6];
    const float* qg  = (const float*)d_in[7];
    const float* qbe = (const float*)d_in[8];
    const float* qm  = (const float*)d_in[9];
    const float* qva = (const float*)d_in[10];
    const float* kg  = (const float*)d_in[11];
    const float* kbe = (const float*)d_in[12];
    const float* km  = (const float*)d_in[13];
    const float* kva = (const float*)d_in[14];
    const float* vg  = (const float*)d_in[15];
    const float* vbe = (const float*)d_in[16];
    const float* vm  = (const float*)d_in[17];
    const float* vva = (const float*)d_in[18];
    const float* pg  = (const float*)d_in[19];
    const float* pbe = (const float*)d_in[20];
    const float* pm  = (const float*)d_in[21];
    const float* pva = (const float*)d_in[22];
    float* out = (float*)d_out;

    cudaFuncSetAttribute(fused_qkv_kernel, cudaFuncAttributeMaxDynamicSharedMemorySize, FSMEM);
    cudaFuncSetAttribute(gemm_proj_kernel, cudaFuncAttributeMaxDynamicSharedMemorySize, PJSMEM);

    split_w_kernel<<<(4 * kW + 255) / 256, 256>>>(qw, kw, vw, pw);

    lif_x_kernel<<<dim3(kN / 32, kC / 32, kB), 256>>>(x);

    fused_qkv_kernel<<<dim3(kN / 64, 9, kB), 256, FSMEM>>>(
        qg, qbe, qm, qva, kg, kbe, km, kva, vg, vbe, vm, vva);

    kvsum_kernel<<<kT * kB * kC / 8, 256>>>();

    kv_kernel<<<1, 384>>>(thw);

    gemm_proj_kernel<<<dim3(kN / 64, kC / 128, kT * kB), 256, PJSMEM>>>(
        pg, pbe, pm, pva, pb, x, out);
}

// round 12
// speedup vs baseline: 1.9015x; 1.9015x over previous
#include <cuda_runtime.h>
#include <cuda_fp16.h>
#include <cstdint>
#include <math.h>

constexpr int kT = 4, kB = 8, kC = 384, kN = 1024;
constexpr int kBCN  = kB * kC * kN;
constexpr int kTBCN = kT * kBCN;
constexpr float kEPS = 1e-5f;
constexpr int kWelems = kC * kC;            // 147456
constexpr float kLoScale = 1.0f / 4096.0f;

// ---------------- device scratch ----------------
__device__ __half g_wqkv[6 * kWelems];      // [branch*2+split][m][k]  (hi, lo*4096)
__device__ __half g_wp[2 * kWelems];        // [split][m][k] (proj uses hi only)
__device__ __half g_sx[kTBCN];              // input spikes  [t][b][n][c]
__device__ __half g_qb[kTBCN];              // q spikes      [t][b][n][c]
__device__ __half g_kb[kTBCN];              // k spikes      [t][b][c][n]
__device__ __half g_vb[kTBCN];              // v spikes      [t][b][c][n]
__device__ float g_kvsum[kT * kB * kC];
__device__ __half g_kvsh[kT * kB * kC];     // kv spikes (fp16)

// ---------------- helpers ----------------
__device__ __forceinline__ uint32_t smem_u32(const void* p) {
    uint32_t a;
    asm("{ .reg .u64 t; cvta.to.shared.u64 t, %1; cvt.u32.u64 %0, t; }" : "=r"(a) : "l"(p));
    return a;
}
__device__ __forceinline__ void cp16(uint32_t dst, const void* src) {
    asm volatile("cp.async.cg.shared.global [%0], [%1], 16;" :: "r"(dst), "l"(src));
}
__device__ __forceinline__ void ldm_x4(uint32_t* r, uint32_t addr) {
    asm volatile("ldmatrix.sync.aligned.m8n8.x4.shared.b16 {%0,%1,%2,%3}, [%4];"
                 : "=r"(r[0]), "=r"(r[1]), "=r"(r[2]), "=r"(r[3]) : "r"(addr));
}
__device__ __forceinline__ void mma16816(float* c, const uint32_t* a, uint32_t b0, uint32_t b1) {
    asm volatile("mma.sync.aligned.m16n8k16.row.col.f32.f16.f16.f32 "
                 "{%0,%1,%2,%3}, {%4,%5,%6,%7}, {%8,%9}, {%0,%1,%2,%3};"
                 : "+f"(c[0]), "+f"(c[1]), "+f"(c[2]), "+f"(c[3])
                 : "r"(a[0]), "r"(a[1]), "r"(a[2]), "r"(a[3]), "r"(b0), "r"(b1));
}
__device__ __forceinline__ uint32_t hmul2u(uint32_t a, uint32_t b) {
    __half2 r = __hmul2(*(__half2*)&a, *(__half2*)&b);
    return *(uint32_t*)&r;
}

// ---- fused QKV tiling: 128(M) x 64(N) x 48(K), 8 warps (4m x 2n) ----
constexpr int BM = 128, BN = 64, FBK = 48;
constexpr int FPITCH = 56;                         // halves per row (112B, conflict-free)
constexpr int FA_ELEMS = 2 * BM * FPITCH;          // 14336 halves (2 splits)
constexpr int FB_ELEMS = BN * FPITCH;              // 3584
constexpr int FSTAGE_ELEMS = FA_ELEMS + FB_ELEMS;  // 17920
constexpr int FSTAGE_BYTES = FSTAGE_ELEMS * 2;     // 35840
constexpr int VST_OFF = 2 * FSTAGE_BYTES;          // 71680
constexpr int FSMEM   = VST_OFF + 256 * 32 * 4;    // 104448
// spike staging aliases stage 1 (dead during epilogue); pitches in halves
constexpr int QPITCH = 136;
constexpr int KVP    = 72;

// ---- proj tiling (unchanged from R9): BK=32, PITCH=40, hi split only ----
constexpr int PBK = 32;
constexpr int PPITCH = 40;
constexpr int PJA_ELEMS = BM * PPITCH;                 // 5120
constexpr int PJB_ELEMS = BN * PPITCH;                 // 2560
constexpr int PJSTAGE_ELEMS = PJA_ELEMS + PJB_ELEMS;   // 7680
constexpr int PJSTAGE_BYTES = PJSTAGE_ELEMS * 2;       // 15360
constexpr int PJSMEM = 2 * PJSTAGE_BYTES;              // 30720

// ---------------------------------------------------------------------------
// K0: split fp32 weights into (hi, lo*4096) fp16 pair.
// ---------------------------------------------------------------------------
__global__ void split_w_kernel(const float* __restrict__ qw, const float* __restrict__ kw,
                               const float* __restrict__ vw, const float* __restrict__ pw) {
    int idx = blockIdx.x * 256 + threadIdx.x;
    if (idx >= 4 * kWelems) return;
    int mat = idx / kWelems;
    int e = idx - mat * kWelems;
    const float* src = (mat == 0) ? qw : (mat == 1) ? kw : (mat == 2) ? vw : pw;
    float w = src[e];
    __half h = __float2half_rn(w);
    __half l = __float2half_rn((w - __half2float(h)) * 4096.0f);
    if (mat < 3) {
        g_wqkv[(mat * 2 + 0) * kWelems + e] = h;
        g_wqkv[(mat * 2 + 1) * kWelems + e] = l;
    } else {
        g_wp[0 * kWelems + e] = h;
        g_wp[1 * kWelems + e] = l;
    }
}

// ---------------------------------------------------------------------------
// K1: LIF on x [t][b][c][n] -> fp16 spikes transposed to [t][b][n][c].
// ---------------------------------------------------------------------------
__global__ void lif_x_kernel(const float* __restrict__ x) {
    __shared__ __half sm[32][36];
    const int lane = threadIdx.x & 31, wid = threadIdx.x >> 5;
    const int n0 = blockIdx.x * 32, c0 = blockIdx.y * 32, b = blockIdx.z;
    float v[4] = {0.f, 0.f, 0.f, 0.f};
    for (int t = 0; t < kT; t++) {
#pragma unroll
        for (int j = 0; j < 4; j++) {
            int c = c0 + wid * 4 + j;
            float xv = x[((size_t)((t * kB + b) * kC + c)) * kN + n0 + lane];
            v[j] += (xv - v[j]) * 0.5f;
            float s = 0.f;
            if (v[j] >= 0.5f) { s = 1.f; v[j] = 0.f; }
            sm[lane][wid * 4 + j] = __float2half(s);
        }
        __syncthreads();
        int nr = wid * 4 + (lane >> 3);
        int cw = (lane & 7) * 4;
        uint2 val = *(const uint2*)&sm[nr][cw];
        *(uint2*)&g_sx[((size_t)((t * kB + b) * kN + n0 + nr)) * kC + c0 + cw] = val;
        __syncthreads();
    }
}

// ---------------------------------------------------------------------------
// FUSED QKV: grid (16 ntiles, 9 = p*3+mtile, 8 b).
// Per t: dual-split fp16 GEMM over K=384 in 8 chunks of 48 (fewer barrier
// rounds than BK=32), BN + LIF epilogue, spikes staged for coalesced stores.
// Prefetches (t+1, chunk0) during t's tail.
// ---------------------------------------------------------------------------
__global__ __launch_bounds__(256, 2) void fused_qkv_kernel(
    const float* __restrict__ qg, const float* __restrict__ qbe, const float* __restrict__ qm, const float* __restrict__ qva,
    const float* __restrict__ kg, const float* __restrict__ kbe, const float* __restrict__ km, const float* __restrict__ kva,
    const float* __restrict__ vg, const float* __restrict__ vbe, const float* __restrict__ vm, const float* __restrict__ vva)
{
    extern __shared__ char dynsm[];
    const uint32_t shb = smem_u32(dynsm);
    float* vsm = (float*)(dynsm + VST_OFF);
    __half* stg = (__half*)(dynsm + FSTAGE_BYTES);   // aliases stage 1

    const int tid = threadIdx.x, wid = tid >> 5, lane = tid & 31;
    const int b = blockIdx.z;
    const int yy = blockIdx.y;
    const int p = (yy >= 6) ? 2 : ((yy >= 3) ? 1 : 0);
    const int mtile = yy - p * 3;
    const int m0 = mtile * BM, n0 = blockIdx.x * BN;

    const __half* Abase = g_wqkv + (size_t)(p * 2) * kWelems;
    const int mw = wid >> 1, nw = wid & 1;
    const int gr = lane >> 2, gc = (lane & 3) * 2;
    const int ldrow = lane & 15, ldhalf = lane >> 4;

    const float *G, *Be, *Mn, *Va;
    if (p == 0)      { G = qg; Be = qbe; Mn = qm; Va = qva; }
    else if (p == 1) { G = kg; Be = kbe; Mn = km; Va = kva; }
    else             { G = vg; Be = vbe; Mn = vm; Va = vva; }
    float scv[2][2], mnv[2][2], bev[2][2];
#pragma unroll
    for (int mi = 0; mi < 2; mi++)
#pragma unroll
        for (int half = 0; half < 2; half++) {
            int cc = m0 + mw * 32 + mi * 16 + half * 8 + gr;
            scv[mi][half] = G[cc] / sqrtf(Va[cc] + kEPS);
            mnv[mi][half] = Mn[cc];
            bev[mi][half] = Be[cc];
        }

#pragma unroll
    for (int j = 0; j < 32; j++) vsm[j * 256 + tid] = 0.f;

    // chunk loader: K-chunk ck (48 wide) of timestep t into stage st.
    // A: 2 splits x 128 rows x 6 x 16B = 1536 cp16 (6/thread)
    // B: 64 rows x 6 x 16B = 384 cp16
    auto load_chunk = [&](int t, int ck, int st) {
        const uint32_t sb = shb + st * FSTAGE_BYTES;
        const int k0 = ck * FBK;
#pragma unroll
        for (int it = 0; it < 6; it++) {
            int i = it * 256 + tid;
            int sp = i / 768, rem = i % 768;
            int r = rem / 6, seg = rem % 6;
            cp16(sb + ((sp * BM + r) * FPITCH + seg * 8) * 2,
                 Abase + (size_t)sp * kWelems + (size_t)(m0 + r) * kC + k0 + seg * 8);
        }
#pragma unroll
        for (int it = 0; it < 2; it++) {
            int i = it * 256 + tid;
            if (i < 384) {
                int r = i / 6, seg = i % 6;
                cp16(sb + (FA_ELEMS + r * FPITCH + seg * 8) * 2,
                     g_sx + ((size_t)(t * kB + b) * kN + n0 + r) * kC + k0 + seg * 8);
            }
        }
        asm volatile("cp.async.commit_group;");
    };

    load_chunk(0, 0, 0);
    for (int t = 0; t < kT; t++) {
        float acch[2][4][4], accl[2][4][4];
#pragma unroll
        for (int i = 0; i < 2; i++)
#pragma unroll
            for (int j = 0; j < 4; j++)
#pragma unroll
                for (int q = 0; q < 4; q++) { acch[i][j][q] = 0.f; accl[i][j][q] = 0.f; }

        for (int cch = 0; cch < kC / FBK; cch++) {
            if (cch + 1 < kC / FBK) {
                load_chunk(t, cch + 1, (cch + 1) & 1);
                asm volatile("cp.async.wait_group 1;");
            } else {
                if (t + 1 < kT) {
                    load_chunk(t + 1, 0, 0);
                    asm volatile("cp.async.wait_group 1;");
                } else {
                    asm volatile("cp.async.wait_group 0;");
                }
            }
            __syncthreads();
            const uint32_t sb = shb + (cch & 1) * FSTAGE_BYTES;
#pragma unroll
            for (int ks = 0; ks < 3; ks++) {
                const int k0 = ks * 16;
                uint32_t bfr[2][4];
#pragma unroll
                for (int g = 0; g < 2; g++)
                    ldm_x4(bfr[g], sb + (FA_ELEMS + (nw * 32 + g * 16 + ldrow) * FPITCH + k0 + ldhalf * 8) * 2);
#pragma unroll
                for (int sp = 0; sp < 2; sp++) {
                    uint32_t afr[2][4];
#pragma unroll
                    for (int mi = 0; mi < 2; mi++)
                        ldm_x4(afr[mi], sb + ((sp * BM + mw * 32 + mi * 16 + ldrow) * FPITCH + k0 + ldhalf * 8) * 2);
#pragma unroll
                    for (int mi = 0; mi < 2; mi++)
#pragma unroll
                        for (int nj = 0; nj < 4; nj++) {
                            int g = nj >> 1, w = nj & 1;
                            float* acc = (sp == 0) ? acch[mi][nj] : accl[mi][nj];
                            mma16816(acc, afr[mi], bfr[g][w], bfr[g][w + 2]);
                        }
                }
            }
            __syncthreads();
        }

        // ---- BN + LIF epilogue for timestep t ----
#pragma unroll
        for (int mi = 0; mi < 2; mi++)
#pragma unroll
            for (int nj = 0; nj < 4; nj++)
#pragma unroll
                for (int q = 0; q < 4; q++) {
                    const int half = q >> 1;
                    const int j = mi * 16 + nj * 4 + q;
                    float u = (acch[mi][nj][q] + accl[mi][nj][q] * kLoScale - mnv[mi][half]) * scv[mi][half] + bev[mi][half];
                    float vv = vsm[j * 256 + tid];
                    vv += (u - vv) * 0.5f;
                    float s = 0.f;
                    if (vv >= 0.5f) { s = 1.f; vv = 0.f; }
                    vsm[j * 256 + tid] = vv;

                    const int cl = mw * 32 + mi * 16 + half * 8 + gr;
                    const int n = nw * 32 + nj * 8 + gc + (q & 1);
                    if (p == 0) stg[n * QPITCH + cl] = __float2half(s);
                    else        stg[cl * KVP + n]   = __float2half(s);
                }

        __syncthreads();
        if (p == 0) {
#pragma unroll
            for (int it = 0; it < 4; it++) {
                int i = it * 256 + tid;
                int n = i >> 4, w = i & 15;
                uint4 val = *(const uint4*)&stg[n * QPITCH + w * 8];
                *(uint4*)&g_qb[((size_t)((t * kB + b) * kN + n0 + n)) * kC + m0 + w * 8] = val;
            }
        } else {
            __half* dstb = (p == 1) ? g_kb : g_vb;
#pragma unroll
            for (int it = 0; it < 4; it++) {
                int i = it * 256 + tid;
                int cl = i >> 3, w = i & 7;
                uint4 val = *(const uint4*)&stg[cl * KVP + w * 8];
                *(uint4*)&dstb[((size_t)((t * kB + b) * kC + m0 + cl)) * kN + n0 + w * 8] = val;
            }
        }
        __syncthreads();
    }
}

// ---------------------------------------------------------------------------
// kvsum: one warp per (t,b,c) row: sum_n k*v (binary fp16 -> exact).
// ---------------------------------------------------------------------------
__global__ void kvsum_kernel() {
    const int row = blockIdx.x * 8 + (threadIdx.x >> 5);
    const int lane = threadIdx.x & 31;
    const uint2* kp = (const uint2*)(g_kb + (size_t)row * kN);
    const uint2* vp = (const uint2*)(g_vb + (size_t)row * kN);
    float s = 0.f;
#pragma unroll
    for (int i = lane; i < kN / 4; i += 32) {
        uint2 kv4 = kp[i], vv4 = vp[i];
        __half2 p0 = __hmul2(*(__half2*)&kv4.x, *(__half2*)&vv4.x);
        __half2 p1 = __hmul2(*(__half2*)&kv4.y, *(__half2*)&vv4.y);
        float2 f0 = __half22float2(p0), f1 = __half22float2(p1);
        s += (f0.x + f0.y) + (f1.x + f1.y);
    }
#pragma unroll
    for (int o = 16; o; o >>= 1) s += __shfl_xor_sync(0xffffffffu, s, o);
    if (lane == 0) g_kvsum[row] = s;
}

// ---------------------------------------------------------------------------
// K4: talking heads + LIF on kv; kv spikes -> fp16.
// ---------------------------------------------------------------------------
__global__ void kv_kernel(const float* __restrict__ th_w) {
    __shared__ float th[64];
    if (threadIdx.x < 64) th[threadIdx.x] = th_w[threadIdx.x];
    __syncthreads();
    int d = threadIdx.x % 48;
    int b = threadIdx.x / 48;
    float v[8];
#pragma unroll
    for (int o = 0; o < 8; o++) v[o] = 0.0f;
#pragma unroll
    for (int t = 0; t < kT; t++) {
        float kvv[8];
#pragma unroll
        for (int h = 0; h < 8; h++)
            kvv[h] = g_kvsum[(t * kB + b) * kC + h * 48 + d];
#pragma unroll
        for (int o = 0; o < 8; o++) {
            float a = 0.0f;
#pragma unroll
            for (int h = 0; h < 8; h++) a += th[o * 8 + h] * kvv[h];
            v[o] += (a - v[o]) * 0.5f;
            float s = 0.f;
            if (v[o] >= 0.5f) { s = 1.f; v[o] = 0.f; }
            g_kvsh[(t * kB + b) * kC + o * 48 + d] = __float2half(s);
        }
    }
}

// ---------------------------------------------------------------------------
// PROJ GEMM: hi-split only; B = q spikes * kvs (folded post-ldmatrix, exact).
// Epilogue: +bias, BN, +identity.   (identical to R9)
// ---------------------------------------------------------------------------
__global__ __launch_bounds__(256, 3) void gemm_proj_kernel(
    const float* __restrict__ pg, const float* __restrict__ pbe,
    const float* __restrict__ pm, const float* __restrict__ pva,
    const float* __restrict__ bias, const float* __restrict__ xres, float* __restrict__ outp)
{
    extern __shared__ __half sh[];
    const uint32_t shb = smem_u32(sh);

    const int tid = threadIdx.x, wid = tid >> 5, lane = tid & 31;
    const int bz = blockIdx.z, t = bz >> 3, b = bz & 7;
    const int m0 = blockIdx.y * BM, n0 = blockIdx.x * BN;

    const __half* Bimg = g_qb + (size_t)(t * kB + b) * kN * kC;
    const uint32_t* kvsp = (const uint32_t*)(g_kvsh + (t * kB + b) * kC);

    const int mw = wid >> 1, nw = wid & 1;

    float acch[2][4][4];
#pragma unroll
    for (int i = 0; i < 2; i++)
#pragma unroll
        for (int j = 0; j < 4; j++)
#pragma unroll
            for (int q = 0; q < 4; q++) acch[i][j][q] = 0.f;

    auto load_chunk = [&](int ck, int st) {
        const uint32_t sb = shb + st * PJSTAGE_BYTES;
        const int k0 = ck * PBK;
#pragma unroll
        for (int it = 0; it < 2; it++) {
            int i = it * 256 + tid;
            int r = i >> 2, kq = i & 3;
            cp16(sb + (r * PPITCH + kq * 8) * 2,
                 g_wp + (size_t)(m0 + r) * kC + k0 + kq * 8);
        }
        {
            int r = tid >> 2, kq = tid & 3;
            cp16(sb + (PJA_ELEMS + r * PPITCH + kq * 8) * 2,
                 Bimg + (size_t)(n0 + r) * kC + k0 + kq * 8);
        }
        asm volatile("cp.async.commit_group;");
    };

    load_chunk(0, 0);
    const int ldrow = lane & 15, ldhalf = lane >> 4;

    for (int cch = 0; cch < kC / PBK; cch++) {
        if (cch + 1 < kC / PBK) {
            load_chunk(cch + 1, (cch + 1) & 1);
            asm volatile("cp.async.wait_group 1;");
        } else {
            asm volatile("cp.async.wait_group 0;");
        }
        __syncthreads();
        const uint32_t sb = shb + (cch & 1) * PJSTAGE_BYTES;
#pragma unroll
        for (int ks = 0; ks < 2; ks++) {
            const int k0 = ks * 16;
            uint32_t bfr[2][4];
#pragma unroll
            for (int g = 0; g < 2; g++)
                ldm_x4(bfr[g], sb + (PJA_ELEMS + (nw * 32 + g * 16 + ldrow) * PPITCH + k0 + ldhalf * 8) * 2);
            {
                uint32_t p0 = kvsp[cch * 16 + ks * 8 + (lane & 3)];
                uint32_t p1 = kvsp[cch * 16 + ks * 8 + 4 + (lane & 3)];
#pragma unroll
                for (int g = 0; g < 2; g++) {
                    bfr[g][0] = hmul2u(bfr[g][0], p0);
                    bfr[g][1] = hmul2u(bfr[g][1], p0);
                    bfr[g][2] = hmul2u(bfr[g][2], p1);
                    bfr[g][3] = hmul2u(bfr[g][3], p1);
                }
            }
            uint32_t afr[2][4];
#pragma unroll
            for (int mi = 0; mi < 2; mi++)
                ldm_x4(afr[mi], sb + ((mw * 32 + mi * 16 + ldrow) * PPITCH + k0 + ldhalf * 8) * 2);
#pragma unroll
            for (int mi = 0; mi < 2; mi++)
#pragma unroll
                for (int nj = 0; nj < 4; nj++) {
                    int g = nj >> 1, w = nj & 1;
                    mma16816(acch[mi][nj], afr[mi], bfr[g][w], bfr[g][w + 2]);
                }
        }
        __syncthreads();
    }

    const int gr = lane >> 2, gc = (lane & 3) * 2;
    const size_t imgoff = ((size_t)(t * kB + b) * kC) * kN;

#pragma unroll
    for (int mi = 0; mi < 2; mi++) {
#pragma unroll
        for (int half = 0; half < 2; half++) {
            const int c = m0 + mw * 32 + mi * 16 + gr + half * 8;
            const float sc = pg[c] / sqrtf(pva[c] + kEPS);
            const float mn = pm[c], be = pbe[c];
            const float bi = bias[c];
            size_t rowoff = imgoff + (size_t)c * kN;
            float* dst = outp + rowoff;
#pragma unroll
            for (int nj = 0; nj < 4; nj++) {
                const int n = n0 + nw * 32 + nj * 8 + gc;
                float v0 = acch[mi][nj][half * 2 + 0];
                float v1 = acch[mi][nj][half * 2 + 1];
                float2 xv = *(const float2*)(xres + rowoff + n);
                float2 o;
                o.x = ((v0 + bi) - mn) * sc + be + xv.x;
                o.y = ((v1 + bi) - mn) * sc + be + xv.y;
                *(float2*)(dst + n) = o;
            }
        }
    }
}

// ---------------------------------------------------------------------------
extern "C" void kernel_launch(void* const* d_in, const int* in_sizes, int n_in,
                              void* d_out, int out_size)
{
    const float* x   = (const float*)d_in[0];
    const float* qw  = (const float*)d_in[1];
    const float* kw  = (const float*)d_in[2];
    const float* vw  = (const float*)d_in[3];
    const float* thw = (const float*)d_in[4];
    const float* pw  = (const float*)d_in[5];
    const float* pb  = (const float*)d_in[6];
    const float* qg  = (const float*)d_in[7];
    const float* qbe = (const float*)d_in[8];
    const float* qm  = (const float*)d_in[9];
    const float* qva = (const float*)d_in[10];
    const float* kg  = (const float*)d_in[11];
    const float* kbe = (const float*)d_in[12];
    const float* km  = (const float*)d_in[13];
    const float* kva = (const float*)d_in[14];
    const float* vg  = (const float*)d_in[15];
    const float* vbe = (const float*)d_in[16];
    const float* vm  = (const float*)d_in[17];
    const float* vva = (const float*)d_in[18];
    const float* pg  = (const float*)d_in[19];
    const float* pbe = (const float*)d_in[20];
    const float* pm  = (const float*)d_in[21];
    const float* pva = (const float*)d_in[22];
    float* out = (float*)d_out;

    cudaFuncSetAttribute(fused_qkv_kernel, cudaFuncAttributeMaxDynamicSharedMemorySize, FSMEM);
    cudaFuncSetAttribute(gemm_proj_kernel, cudaFuncAttributeMaxDynamicSharedMemorySize, PJSMEM);

    split_w_kernel<<<(4 * kWelems + 255) / 256, 256>>>(qw, kw, vw, pw);

    lif_x_kernel<<<dim3(kN / 32, kC / 32, kB), 256>>>(x);

    fused_qkv_kernel<<<dim3(kN / BN, 9, kB), 256, FSMEM>>>(
        qg, qbe, qm, qva, kg, kbe, km, kva, vg, vbe, vm, vva);

    kvsum_kernel<<<kT * kB * kC / 8, 256>>>();

    kv_kernel<<<1, 384>>>(thw);

    gemm_proj_kernel<<<dim3(kN / BN, kC / BM, kT * kB), 256, PJSMEM>>>(
        pg, pbe, pm, pva, pb, x, out);
}

// round 13
// speedup vs baseline: 3.0016x; 1.5786x over previous
#include <cuda_runtime.h>
#include <cuda_fp16.h>
#include <cstdint>
#include <math.h>

constexpr int kT = 4, kB = 8, kC = 384, kN = 1024;
constexpr int kBCN  = kB * kC * kN;
constexpr int kTBCN = kT * kBCN;
constexpr float kEPS = 1e-5f;
constexpr int kWelems = kC * kC;            // 147456
constexpr float kLoScale = 1.0f / 4096.0f;

// ---------------- device scratch ----------------
__device__ __half g_wqkv[6 * kWelems];      // [branch*2+split][m][k]  (hi, lo*4096)
__device__ __half g_wp[2 * kWelems];        // [split][m][k] (proj uses hi only)
__device__ __half g_sx[kTBCN];              // input spikes  [t][b][n][c]
__device__ __half g_qb[kTBCN];              // q spikes      [t][b][n][c]
__device__ __half g_kb[kTBCN];              // k spikes      [t][b][c][n]
__device__ __half g_vb[kTBCN];              // v spikes      [t][b][c][n]
__device__ float g_kvsum[kT * kB * kC];
__device__ __half g_kvsh[kT * kB * kC];     // kv spikes (fp16)

// ---------------- helpers ----------------
__device__ __forceinline__ uint32_t smem_u32(const void* p) {
    uint32_t a;
    asm("{ .reg .u64 t; cvta.to.shared.u64 t, %1; cvt.u32.u64 %0, t; }" : "=r"(a) : "l"(p));
    return a;
}
__device__ __forceinline__ void cp16(uint32_t dst, const void* src) {
    asm volatile("cp.async.cg.shared.global [%0], [%1], 16;" :: "r"(dst), "l"(src));
}
__device__ __forceinline__ void ldm_x4(uint32_t* r, uint32_t addr) {
    asm volatile("ldmatrix.sync.aligned.m8n8.x4.shared.b16 {%0,%1,%2,%3}, [%4];"
                 : "=r"(r[0]), "=r"(r[1]), "=r"(r[2]), "=r"(r[3]) : "r"(addr));
}
__device__ __forceinline__ void mma16816(float* c, const uint32_t* a, uint32_t b0, uint32_t b1) {
    asm volatile("mma.sync.aligned.m16n8k16.row.col.f32.f16.f16.f32 "
                 "{%0,%1,%2,%3}, {%4,%5,%6,%7}, {%8,%9}, {%0,%1,%2,%3};"
                 : "+f"(c[0]), "+f"(c[1]), "+f"(c[2]), "+f"(c[3])
                 : "r"(a[0]), "r"(a[1]), "r"(a[2]), "r"(a[3]), "r"(b0), "r"(b1));
}
__device__ __forceinline__ uint32_t hmul2u(uint32_t a, uint32_t b) {
    __half2 r = __hmul2(*(__half2*)&a, *(__half2*)&b);
    return *(uint32_t*)&r;
}

// GEMM tiling: 128(M) x 64(N) x 32(K), 8 warps (4m x 2n), dual-split accumulation.
constexpr int BM = 128, BN = 64, BK = 32;
constexpr int PITCH = 40;                        // half elems per smem row (80B)
constexpr int A_ELEMS = 2 * BM * PITCH;          // 10240 (2 splits)
constexpr int B_ELEMS = BN * PITCH;              // 2560
constexpr int STAGE_ELEMS = A_ELEMS + B_ELEMS;   // 12800
constexpr int STAGE_BYTES = STAGE_ELEMS * 2;     // 25600
// fused kernel smem: 3 stages + LIF-state (256 threads x 32 floats)
constexpr int VST_OFF  = 3 * STAGE_BYTES;        // 76800
constexpr int FSMEM    = VST_OFF + 256 * 32 * 4; // 109568
// spike staging aliases stage 1 (free during epilogue); pitches in halves
constexpr int QPITCH = 136;
constexpr int KVP    = 72;

// proj kernel: 2 stages, hi split only (R9)
constexpr int PJA_ELEMS = BM * PITCH;                 // 5120
constexpr int PJSTAGE_ELEMS = PJA_ELEMS + B_ELEMS;    // 7680
constexpr int PJSTAGE_BYTES = PJSTAGE_ELEMS * 2;      // 15360
constexpr int PJSMEM = 2 * PJSTAGE_BYTES;             // 30720

// ---------------------------------------------------------------------------
// K0: split fp32 weights into (hi, lo*4096) fp16 pair.
// ---------------------------------------------------------------------------
__global__ void split_w_kernel(const float* __restrict__ qw, const float* __restrict__ kw,
                               const float* __restrict__ vw, const float* __restrict__ pw) {
    int idx = blockIdx.x * 256 + threadIdx.x;
    if (idx >= 4 * kWelems) return;
    int mat = idx / kWelems;
    int e = idx - mat * kWelems;
    const float* src = (mat == 0) ? qw : (mat == 1) ? kw : (mat == 2) ? vw : pw;
    float w = src[e];
    __half h = __float2half_rn(w);
    __half l = __float2half_rn((w - __half2float(h)) * 4096.0f);
    if (mat < 3) {
        g_wqkv[(mat * 2 + 0) * kWelems + e] = h;
        g_wqkv[(mat * 2 + 1) * kWelems + e] = l;
    } else {
        g_wp[0 * kWelems + e] = h;
        g_wp[1 * kWelems + e] = l;
    }
}

// ---------------------------------------------------------------------------
// K1: LIF on x [t][b][c][n] -> fp16 spikes transposed to [t][b][n][c].
// ---------------------------------------------------------------------------
__global__ void lif_x_kernel(const float* __restrict__ x) {
    __shared__ __half sm[32][36];
    const int lane = threadIdx.x & 31, wid = threadIdx.x >> 5;
    const int n0 = blockIdx.x * 32, c0 = blockIdx.y * 32, b = blockIdx.z;
    float v[4] = {0.f, 0.f, 0.f, 0.f};
    for (int t = 0; t < kT; t++) {
#pragma unroll
        for (int j = 0; j < 4; j++) {
            int c = c0 + wid * 4 + j;
            float xv = x[((size_t)((t * kB + b) * kC + c)) * kN + n0 + lane];
            v[j] += (xv - v[j]) * 0.5f;
            float s = 0.f;
            if (v[j] >= 0.5f) { s = 1.f; v[j] = 0.f; }
            sm[lane][wid * 4 + j] = __float2half(s);
        }
        __syncthreads();
        int nr = wid * 4 + (lane >> 3);
        int cw = (lane & 7) * 4;
        uint2 val = *(const uint2*)&sm[nr][cw];
        *(uint2*)&g_sx[((size_t)((t * kB + b) * kN + n0 + nr)) * kC + c0 + cw] = val;
        __syncthreads();
    }
}

// ---------------------------------------------------------------------------
// FUSED QKV: grid (16 ntiles, 9 = p*3+mtile, 8 b).
// 3-stage cp.async pipeline, ONE __syncthreads per chunk.
// Stage schedule per t: cch%3. Last chunk -> stage 2; t+1 chunk0 prefetch ->
// stage 0; stage 1 is FREE during epilogue -> spike staging aliases it.
// (t+1, chunk1) load into stage 1 deferred until after epilogue barrier.
// ---------------------------------------------------------------------------
__global__ __launch_bounds__(256, 2) void fused_qkv_kernel(
    const float* __restrict__ qg, const float* __restrict__ qbe, const float* __restrict__ qm, const float* __restrict__ qva,
    const float* __restrict__ kg, const float* __restrict__ kbe, const float* __restrict__ km, const float* __restrict__ kva,
    const float* __restrict__ vg, const float* __restrict__ vbe, const float* __restrict__ vm, const float* __restrict__ vva)
{
    extern __shared__ char dynsm[];
    const uint32_t shb = smem_u32(dynsm);
    float* vsm = (float*)(dynsm + VST_OFF);
    __half* stg = (__half*)(dynsm + STAGE_BYTES);   // aliases stage 1

    const int tid = threadIdx.x, wid = tid >> 5, lane = tid & 31;
    const int b = blockIdx.z;
    const int yy = blockIdx.y;
    const int p = (yy >= 6) ? 2 : ((yy >= 3) ? 1 : 0);
    const int mtile = yy - p * 3;
    const int m0 = mtile * BM, n0 = blockIdx.x * BN;

    const __half* Abase = g_wqkv + (size_t)(p * 2) * kWelems;
    const int mw = wid >> 1, nw = wid & 1;
    const int gr = lane >> 2, gc = (lane & 3) * 2;
    const int ldrow = lane & 15, ldhalf = lane >> 4;

    const float *G, *Be, *Mn, *Va;
    if (p == 0)      { G = qg; Be = qbe; Mn = qm; Va = qva; }
    else if (p == 1) { G = kg; Be = kbe; Mn = km; Va = kva; }
    else             { G = vg; Be = vbe; Mn = vm; Va = vva; }
    float scv[2][2], mnv[2][2], bev[2][2];
#pragma unroll
    for (int mi = 0; mi < 2; mi++)
#pragma unroll
        for (int half = 0; half < 2; half++) {
            int cc = m0 + mw * 32 + mi * 16 + half * 8 + gr;
            scv[mi][half] = G[cc] / sqrtf(Va[cc] + kEPS);
            mnv[mi][half] = Mn[cc];
            bev[mi][half] = Be[cc];
        }

#pragma unroll
    for (int j = 0; j < 32; j++) vsm[j * 256 + tid] = 0.f;

    // chunk loader (identical addressing to R9), explicit stage index
    auto load_chunk = [&](int t, int ck, int st) {
        const uint32_t sb = shb + st * STAGE_BYTES;
        const int k0 = ck * BK;
#pragma unroll
        for (int it = 0; it < 4; it++) {
            int i = it * 256 + tid;
            int sp = i >> 9, rem = i & 511, r = rem >> 2, kq = rem & 3;
            cp16(sb + ((sp * BM + r) * PITCH + kq * 8) * 2,
                 Abase + (size_t)sp * kWelems + (size_t)(m0 + r) * kC + k0 + kq * 8);
        }
        {
            int r = tid >> 2, kq = tid & 3;
            cp16(sb + (A_ELEMS + r * PITCH + kq * 8) * 2,
                 g_sx + ((size_t)(t * kB + b) * kN + n0 + r) * kC + k0 + kq * 8);
        }
        asm volatile("cp.async.commit_group;");
    };

    // prologue: chunks 0,1 of t=0 into stages 0,1
    load_chunk(0, 0, 0);
    load_chunk(0, 1, 1);

    for (int t = 0; t < kT; t++) {
        float acch[2][4][4], accl[2][4][4];
#pragma unroll
        for (int i = 0; i < 2; i++)
#pragma unroll
            for (int j = 0; j < 4; j++)
#pragma unroll
                for (int q = 0; q < 4; q++) { acch[i][j][q] = 0.f; accl[i][j][q] = 0.f; }

        for (int cch = 0; cch < 12; cch++) {
            if (t == kT - 1 && cch == 11) {
                asm volatile("cp.async.wait_group 0;");
            } else {
                asm volatile("cp.async.wait_group 1;");
            }
            __syncthreads();
            // issue next-next load AFTER the barrier (its stage was consumed at cch-1)
            if (cch <= 9) {
                load_chunk(t, cch + 2, (cch + 2) % 3);
            } else if (cch == 10 && t < kT - 1) {
                load_chunk(t + 1, 0, 0);
            }
            // compute chunk cch on stage cch%3
            const uint32_t sb = shb + (cch % 3) * STAGE_BYTES;
#pragma unroll
            for (int ks = 0; ks < 2; ks++) {
                const int k0 = ks * 16;
                uint32_t bfr[2][4];
#pragma unroll
                for (int g = 0; g < 2; g++)
                    ldm_x4(bfr[g], sb + (A_ELEMS + (nw * 32 + g * 16 + ldrow) * PITCH + k0 + ldhalf * 8) * 2);
#pragma unroll
                for (int sp = 0; sp < 2; sp++) {
                    uint32_t afr[2][4];
#pragma unroll
                    for (int mi = 0; mi < 2; mi++)
                        ldm_x4(afr[mi], sb + ((sp * BM + mw * 32 + mi * 16 + ldrow) * PITCH + k0 + ldhalf * 8) * 2);
#pragma unroll
                    for (int mi = 0; mi < 2; mi++)
#pragma unroll
                        for (int nj = 0; nj < 4; nj++) {
                            int g = nj >> 1, w = nj & 1;
                            float* acc = (sp == 0) ? acch[mi][nj] : accl[mi][nj];
                            mma16816(acc, afr[mi], bfr[g][w], bfr[g][w + 2]);
                        }
                }
            }
        }

        // ---- BN + LIF epilogue for timestep t (staging aliases stage 1) ----
#pragma unroll
        for (int mi = 0; mi < 2; mi++)
#pragma unroll
            for (int nj = 0; nj < 4; nj++)
#pragma unroll
                for (int q = 0; q < 4; q++) {
                    const int half = q >> 1;
                    const int j = mi * 16 + nj * 4 + q;
                    float u = (acch[mi][nj][q] + accl[mi][nj][q] * kLoScale - mnv[mi][half]) * scv[mi][half] + bev[mi][half];
                    float vv = vsm[j * 256 + tid];
                    vv += (u - vv) * 0.5f;
                    float s = 0.f;
                    if (vv >= 0.5f) { s = 1.f; vv = 0.f; }
                    vsm[j * 256 + tid] = vv;

                    const int cl = mw * 32 + mi * 16 + half * 8 + gr;
                    const int n = nw * 32 + nj * 8 + gc + (q & 1);
                    if (p == 0) stg[n * QPITCH + cl] = __float2half(s);
                    else        stg[cl * KVP + n]   = __float2half(s);
                }

        __syncthreads();
        if (p == 0) {
#pragma unroll
            for (int it = 0; it < 4; it++) {
                int i = it * 256 + tid;
                int n = i >> 4, w = i & 15;
                uint4 val = *(const uint4*)&stg[n * QPITCH + w * 8];
                *(uint4*)&g_qb[((size_t)((t * kB + b) * kN + n0 + n)) * kC + m0 + w * 8] = val;
            }
        } else {
            __half* dstb = (p == 1) ? g_kb : g_vb;
#pragma unroll
            for (int it = 0; it < 4; it++) {
                int i = it * 256 + tid;
                int cl = i >> 3, w = i & 7;
                uint4 val = *(const uint4*)&stg[cl * KVP + w * 8];
                *(uint4*)&dstb[((size_t)((t * kB + b) * kC + m0 + cl)) * kN + n0 + w * 8] = val;
            }
        }
        __syncthreads();
        // deferred (t+1, chunk1) load into stage 1 (now safe: staging done)
        if (t < kT - 1) load_chunk(t + 1, 1, 1);
    }
}

// ---------------------------------------------------------------------------
// kvsum: one warp per (t,b,c) row: sum_n k*v (binary fp16 -> exact).
// ---------------------------------------------------------------------------
__global__ void kvsum_kernel() {
    const int row = blockIdx.x * 8 + (threadIdx.x >> 5);
    const int lane = threadIdx.x & 31;
    const uint2* kp = (const uint2*)(g_kb + (size_t)row * kN);
    const uint2* vp = (const uint2*)(g_vb + (size_t)row * kN);
    float s = 0.f;
#pragma unroll
    for (int i = lane; i < kN / 4; i += 32) {
        uint2 kv4 = kp[i], vv4 = vp[i];
        __half2 p0 = __hmul2(*(__half2*)&kv4.x, *(__half2*)&vv4.x);
        __half2 p1 = __hmul2(*(__half2*)&kv4.y, *(__half2*)&vv4.y);
        float2 f0 = __half22float2(p0), f1 = __half22float2(p1);
        s += (f0.x + f0.y) + (f1.x + f1.y);
    }
#pragma unroll
    for (int o = 16; o; o >>= 1) s += __shfl_xor_sync(0xffffffffu, s, o);
    if (lane == 0) g_kvsum[row] = s;
}

// ---------------------------------------------------------------------------
// K4: talking heads + LIF on kv; kv spikes -> fp16.
// ---------------------------------------------------------------------------
__global__ void kv_kernel(const float* __restrict__ th_w) {
    __shared__ float th[64];
    if (threadIdx.x < 64) th[threadIdx.x] = th_w[threadIdx.x];
    __syncthreads();
    int d = threadIdx.x % 48;
    int b = threadIdx.x / 48;
    float v[8];
#pragma unroll
    for (int o = 0; o < 8; o++) v[o] = 0.0f;
#pragma unroll
    for (int t = 0; t < kT; t++) {
        float kvv[8];
#pragma unroll
        for (int h = 0; h < 8; h++)
            kvv[h] = g_kvsum[(t * kB + b) * kC + h * 48 + d];
#pragma unroll
        for (int o = 0; o < 8; o++) {
            float a = 0.0f;
#pragma unroll
            for (int h = 0; h < 8; h++) a += th[o * 8 + h] * kvv[h];
            v[o] += (a - v[o]) * 0.5f;
            float s = 0.f;
            if (v[o] >= 0.5f) { s = 1.f; v[o] = 0.f; }
            g_kvsh[(t * kB + b) * kC + o * 48 + d] = __float2half(s);
        }
    }
}

// ---------------------------------------------------------------------------
// PROJ GEMM: hi-split only; B = q spikes * kvs (folded post-ldmatrix, exact).
// Epilogue: +bias, BN, +identity.   (identical to R9)
// ---------------------------------------------------------------------------
__global__ __launch_bounds__(256, 3) void gemm_proj_kernel(
    const float* __restrict__ pg, const float* __restrict__ pbe,
    const float* __restrict__ pm, const float* __restrict__ pva,
    const float* __restrict__ bias, const float* __restrict__ xres, float* __restrict__ outp)
{
    extern __shared__ __half sh[];
    const uint32_t shb = smem_u32(sh);

    const int tid = threadIdx.x, wid = tid >> 5, lane = tid & 31;
    const int bz = blockIdx.z, t = bz >> 3, b = bz & 7;
    const int m0 = blockIdx.y * BM, n0 = blockIdx.x * BN;

    const __half* Bimg = g_qb + (size_t)(t * kB + b) * kN * kC;
    const uint32_t* kvsp = (const uint32_t*)(g_kvsh + (t * kB + b) * kC);

    const int mw = wid >> 1, nw = wid & 1;

    float acch[2][4][4];
#pragma unroll
    for (int i = 0; i < 2; i++)
#pragma unroll
        for (int j = 0; j < 4; j++)
#pragma unroll
            for (int q = 0; q < 4; q++) acch[i][j][q] = 0.f;

    auto load_chunk = [&](int ck, int st) {
        const uint32_t sb = shb + st * PJSTAGE_BYTES;
        const int k0 = ck * BK;
#pragma unroll
        for (int it = 0; it < 2; it++) {
            int i = it * 256 + tid;
            int r = i >> 2, kq = i & 3;
            cp16(sb + (r * PITCH + kq * 8) * 2,
                 g_wp + (size_t)(m0 + r) * kC + k0 + kq * 8);
        }
        {
            int r = tid >> 2, kq = tid & 3;
            cp16(sb + (PJA_ELEMS + r * PITCH + kq * 8) * 2,
                 Bimg + (size_t)(n0 + r) * kC + k0 + kq * 8);
        }
        asm volatile("cp.async.commit_group;");
    };

    load_chunk(0, 0);
    const int ldrow = lane & 15, ldhalf = lane >> 4;

    for (int cch = 0; cch < kC / BK; cch++) {
        if (cch + 1 < kC / BK) {
            load_chunk(cch + 1, (cch + 1) & 1);
            asm volatile("cp.async.wait_group 1;");
        } else {
            asm volatile("cp.async.wait_group 0;");
        }
        __syncthreads();
        const uint32_t sb = shb + (cch & 1) * PJSTAGE_BYTES;
#pragma unroll
        for (int ks = 0; ks < 2; ks++) {
            const int k0 = ks * 16;
            uint32_t bfr[2][4];
#pragma unroll
            for (int g = 0; g < 2; g++)
                ldm_x4(bfr[g], sb + (PJA_ELEMS + (nw * 32 + g * 16 + ldrow) * PITCH + k0 + ldhalf * 8) * 2);
            {
                uint32_t p0 = kvsp[cch * 16 + ks * 8 + (lane & 3)];
                uint32_t p1 = kvsp[cch * 16 + ks * 8 + 4 + (lane & 3)];
#pragma unroll
                for (int g = 0; g < 2; g++) {
                    bfr[g][0] = hmul2u(bfr[g][0], p0);
                    bfr[g][1] = hmul2u(bfr[g][1], p0);
                    bfr[g][2] = hmul2u(bfr[g][2], p1);
                    bfr[g][3] = hmul2u(bfr[g][3], p1);
                }
            }
            uint32_t afr[2][4];
#pragma unroll
            for (int mi = 0; mi < 2; mi++)
                ldm_x4(afr[mi], sb + ((mw * 32 + mi * 16 + ldrow) * PITCH + k0 + ldhalf * 8) * 2);
#pragma unroll
            for (int mi = 0; mi < 2; mi++)
#pragma unroll
                for (int nj = 0; nj < 4; nj++) {
                    int g = nj >> 1, w = nj & 1;
                    mma16816(acch[mi][nj], afr[mi], bfr[g][w], bfr[g][w + 2]);
                }
        }
        __syncthreads();
    }

    const int gr = lane >> 2, gc = (lane & 3) * 2;
    const size_t imgoff = ((size_t)(t * kB + b) * kC) * kN;

#pragma unroll
    for (int mi = 0; mi < 2; mi++) {
#pragma unroll
        for (int half = 0; half < 2; half++) {
            const int c = m0 + mw * 32 + mi * 16 + gr + half * 8;
            const float sc = pg[c] / sqrtf(pva[c] + kEPS);
            const float mn = pm[c], be = pbe[c];
            const float bi = bias[c];
            size_t rowoff = imgoff + (size_t)c * kN;
            float* dst = outp + rowoff;
#pragma unroll
            for (int nj = 0; nj < 4; nj++) {
                const int n = n0 + nw * 32 + nj * 8 + gc;
                float v0 = acch[mi][nj][half * 2 + 0];
                float v1 = acch[mi][nj][half * 2 + 1];
                float2 xv = *(const float2*)(xres + rowoff + n);
                float2 o;
                o.x = ((v0 + bi) - mn) * sc + be + xv.x;
                o.y = ((v1 + bi) - mn) * sc + be + xv.y;
                *(float2*)(dst + n) = o;
            }
        }
    }
}

// ---------------------------------------------------------------------------
extern "C" void kernel_launch(void* const* d_in, const int* in_sizes, int n_in,
                              void* d_out, int out_size)
{
    const float* x   = (const float*)d_in[0];
    const float* qw  = (const float*)d_in[1];
    const float* kw  = (const float*)d_in[2];
    const float* vw  = (const float*)d_in[3];
    const float* thw = (const float*)d_in[4];
    const float* pw  = (const float*)d_in[5];
    const float* pb  = (const float*)d_in[6];
    const float* qg  = (const float*)d_in[7];
    const float* qbe = (const float*)d_in[8];
    const float* qm  = (const float*)d_in[9];
    const float* qva = (const float*)d_in[10];
    const float* kg  = (const float*)d_in[11];
    const float* kbe = (const float*)d_in[12];
    const float* km  = (const float*)d_in[13];
    const float* kva = (const float*)d_in[14];
    const float* vg  = (const float*)d_in[15];
    const float* vbe = (const float*)d_in[16];
    const float* vm  = (const float*)d_in[17];
    const float* vva = (const float*)d_in[18];
    const float* pg  = (const float*)d_in[19];
    const float* pbe = (const float*)d_in[20];
    const float* pm  = (const float*)d_in[21];
    const float* pva = (const float*)d_in[22];
    float* out = (float*)d_out;

    cudaFuncSetAttribute(fused_qkv_kernel, cudaFuncAttributeMaxDynamicSharedMemorySize, FSMEM);
    cudaFuncSetAttribute(gemm_proj_kernel, cudaFuncAttributeMaxDynamicSharedMemorySize, PJSMEM);

    split_w_kernel<<<(4 * kWelems + 255) / 256, 256>>>(qw, kw, vw, pw);

    lif_x_kernel<<<dim3(kN / 32, kC / 32, kB), 256>>>(x);

    fused_qkv_kernel<<<dim3(kN / BN, 9, kB), 256, FSMEM>>>(
        qg, qbe, qm, qva, kg, kbe, km, kva, vg, vbe, vm, vva);

    kvsum_kernel<<<kT * kB * kC / 8, 256>>>();

    kv_kernel<<<1, 384>>>(thw);

    gemm_proj_kernel<<<dim3(kN / BN, kC / BM, kT * kB), 256, PJSMEM>>>(
        pg, pbe, pm, pva, pb, x, out);
}

// round 14
// speedup vs baseline: 3.2474x; 1.0819x over previous
#include <cuda_runtime.h>
#include <cuda_fp16.h>
#include <cstdint>
#include <math.h>

constexpr int kT = 4, kB = 8, kC = 384, kN = 1024;
constexpr int kBCN  = kB * kC * kN;
constexpr int kTBCN = kT * kBCN;
constexpr float kEPS = 1e-5f;
constexpr int kWelems = kC * kC;            // 147456
constexpr float kLoScale = 1.0f / 4096.0f;

// ---------------- device scratch ----------------
__device__ __half g_wqkv[6 * kWelems];      // [branch*2+split][m][k]  (hi, lo*4096)
__device__ __half g_wp[2 * kWelems];        // [split][m][k] (proj uses hi only)
__device__ __half g_sx[kTBCN];              // input spikes  [t][b][n][c]
__device__ __half g_qb[kTBCN];              // q spikes      [t][b][n][c]
__device__ __half g_kb[kTBCN];              // k spikes      [t][b][c][n]
__device__ __half g_vb[kTBCN];              // v spikes      [t][b][c][n]
__device__ float g_kvsum[kT * kB * kC];
__device__ __half g_kvsh[kT * kB * kC];     // kv spikes (fp16)

// ---------------- helpers ----------------
__device__ __forceinline__ uint32_t smem_u32(const void* p) {
    uint32_t a;
    asm("{ .reg .u64 t; cvta.to.shared.u64 t, %1; cvt.u32.u64 %0, t; }" : "=r"(a) : "l"(p));
    return a;
}
__device__ __forceinline__ void cp16(uint32_t dst, const void* src) {
    asm volatile("cp.async.cg.shared.global [%0], [%1], 16;" :: "r"(dst), "l"(src));
}
__device__ __forceinline__ void ldm_x4(uint32_t* r, uint32_t addr) {
    asm volatile("ldmatrix.sync.aligned.m8n8.x4.shared.b16 {%0,%1,%2,%3}, [%4];"
                 : "=r"(r[0]), "=r"(r[1]), "=r"(r[2]), "=r"(r[3]) : "r"(addr));
}
__device__ __forceinline__ void mma16816(float* c, const uint32_t* a, uint32_t b0, uint32_t b1) {
    asm volatile("mma.sync.aligned.m16n8k16.row.col.f32.f16.f16.f32 "
                 "{%0,%1,%2,%3}, {%4,%5,%6,%7}, {%8,%9}, {%0,%1,%2,%3};"
                 : "+f"(c[0]), "+f"(c[1]), "+f"(c[2]), "+f"(c[3])
                 : "r"(a[0]), "r"(a[1]), "r"(a[2]), "r"(a[3]), "r"(b0), "r"(b1));
}
// fp16-accumulate variant (2 packed half2 accumulator regs)
__device__ __forceinline__ void mma16816h(uint32_t* c, const uint32_t* a, uint32_t b0, uint32_t b1) {
    asm volatile("mma.sync.aligned.m16n8k16.row.col.f16.f16.f16.f16 "
                 "{%0,%1}, {%2,%3,%4,%5}, {%6,%7}, {%0,%1};"
                 : "+r"(c[0]), "+r"(c[1])
                 : "r"(a[0]), "r"(a[1]), "r"(a[2]), "r"(a[3]), "r"(b0), "r"(b1));
}
__device__ __forceinline__ uint32_t hmul2u(uint32_t a, uint32_t b) {
    __half2 r = __hmul2(*(__half2*)&a, *(__half2*)&b);
    return *(uint32_t*)&r;
}

// GEMM tiling: 128(M) x 64(N) x 32(K), 8 warps (4m x 2n), dual-split accumulation.
constexpr int BM = 128, BN = 64, BK = 32;
constexpr int PITCH = 40;                        // half elems per smem row (80B)
constexpr int A_ELEMS = 2 * BM * PITCH;          // 10240 (2 splits)
constexpr int B_ELEMS = BN * PITCH;              // 2560
constexpr int STAGE_ELEMS = A_ELEMS + B_ELEMS;   // 12800
constexpr int STAGE_BYTES = STAGE_ELEMS * 2;     // 25600
// fused kernel smem: 3 stages + LIF-state (256 threads x 32 floats)
constexpr int VST_OFF  = 3 * STAGE_BYTES;        // 76800
constexpr int FSMEM    = VST_OFF + 256 * 32 * 4; // 109568
// spike staging aliases stage 1 (free during epilogue); pitches in halves
constexpr int QPITCH = 136;
constexpr int KVP    = 72;

// proj kernel: 2 stages, hi split only
constexpr int PJA_ELEMS = BM * PITCH;                 // 5120
constexpr int PJSTAGE_ELEMS = PJA_ELEMS + B_ELEMS;    // 7680
constexpr int PJSTAGE_BYTES = PJSTAGE_ELEMS * 2;      // 15360
constexpr int PJSMEM = 2 * PJSTAGE_BYTES;             // 30720

// ---------------------------------------------------------------------------
// K0: split fp32 weights into (hi, lo*4096) fp16 pair.
// ---------------------------------------------------------------------------
__global__ void split_w_kernel(const float* __restrict__ qw, const float* __restrict__ kw,
                               const float* __restrict__ vw, const float* __restrict__ pw) {
    int idx = blockIdx.x * 256 + threadIdx.x;
    if (idx >= 4 * kWelems) return;
    int mat = idx / kWelems;
    int e = idx - mat * kWelems;
    const float* src = (mat == 0) ? qw : (mat == 1) ? kw : (mat == 2) ? vw : pw;
    float w = src[e];
    __half h = __float2half_rn(w);
    __half l = __float2half_rn((w - __half2float(h)) * 4096.0f);
    if (mat < 3) {
        g_wqkv[(mat * 2 + 0) * kWelems + e] = h;
        g_wqkv[(mat * 2 + 1) * kWelems + e] = l;
    } else {
        g_wp[0 * kWelems + e] = h;
        g_wp[1 * kWelems + e] = l;
    }
}

// ---------------------------------------------------------------------------
// K1: LIF on x [t][b][c][n] -> fp16 spikes transposed to [t][b][n][c].
// ---------------------------------------------------------------------------
__global__ void lif_x_kernel(const float* __restrict__ x) {
    __shared__ __half sm[32][36];
    const int lane = threadIdx.x & 31, wid = threadIdx.x >> 5;
    const int n0 = blockIdx.x * 32, c0 = blockIdx.y * 32, b = blockIdx.z;
    float v[4] = {0.f, 0.f, 0.f, 0.f};
    for (int t = 0; t < kT; t++) {
#pragma unroll
        for (int j = 0; j < 4; j++) {
            int c = c0 + wid * 4 + j;
            float xv = x[((size_t)((t * kB + b) * kC + c)) * kN + n0 + lane];
            v[j] += (xv - v[j]) * 0.5f;
            float s = 0.f;
            if (v[j] >= 0.5f) { s = 1.f; v[j] = 0.f; }
            sm[lane][wid * 4 + j] = __float2half(s);
        }
        __syncthreads();
        int nr = wid * 4 + (lane >> 3);
        int cw = (lane & 7) * 4;
        uint2 val = *(const uint2*)&sm[nr][cw];
        *(uint2*)&g_sx[((size_t)((t * kB + b) * kN + n0 + nr)) * kC + c0 + cw] = val;
        __syncthreads();
    }
}

// ---------------------------------------------------------------------------
// FUSED QKV: grid (16 ntiles, 9 = p*3+mtile, 8 b).
// 3-stage cp.async pipeline; hi split -> fp32-acc MMA, lo split -> fp16-acc
// MMA (2x rate, error scaled by 2^-12 -> fp32-class). BN+LIF epilogue with
// spike staging aliasing stage 1.
// ---------------------------------------------------------------------------
__global__ __launch_bounds__(256, 2) void fused_qkv_kernel(
    const float* __restrict__ qg, const float* __restrict__ qbe, const float* __restrict__ qm, const float* __restrict__ qva,
    const float* __restrict__ kg, const float* __restrict__ kbe, const float* __restrict__ km, const float* __restrict__ kva,
    const float* __restrict__ vg, const float* __restrict__ vbe, const float* __restrict__ vm, const float* __restrict__ vva)
{
    extern __shared__ char dynsm[];
    const uint32_t shb = smem_u32(dynsm);
    float* vsm = (float*)(dynsm + VST_OFF);
    __half* stg = (__half*)(dynsm + STAGE_BYTES);   // aliases stage 1

    const int tid = threadIdx.x, wid = tid >> 5, lane = tid & 31;
    const int b = blockIdx.z;
    const int yy = blockIdx.y;
    const int p = (yy >= 6) ? 2 : ((yy >= 3) ? 1 : 0);
    const int mtile = yy - p * 3;
    const int m0 = mtile * BM, n0 = blockIdx.x * BN;

    const __half* Abase = g_wqkv + (size_t)(p * 2) * kWelems;
    const int mw = wid >> 1, nw = wid & 1;
    const int gr = lane >> 2, gc = (lane & 3) * 2;
    const int ldrow = lane & 15, ldhalf = lane >> 4;

    const float *G, *Be, *Mn, *Va;
    if (p == 0)      { G = qg; Be = qbe; Mn = qm; Va = qva; }
    else if (p == 1) { G = kg; Be = kbe; Mn = km; Va = kva; }
    else             { G = vg; Be = vbe; Mn = vm; Va = vva; }
    float scv[2][2], mnv[2][2], bev[2][2];
#pragma unroll
    for (int mi = 0; mi < 2; mi++)
#pragma unroll
        for (int half = 0; half < 2; half++) {
            int cc = m0 + mw * 32 + mi * 16 + half * 8 + gr;
            scv[mi][half] = G[cc] / sqrtf(Va[cc] + kEPS);
            mnv[mi][half] = Mn[cc];
            bev[mi][half] = Be[cc];
        }

#pragma unroll
    for (int j = 0; j < 32; j++) vsm[j * 256 + tid] = 0.f;

    auto load_chunk = [&](int t, int ck, int st) {
        const uint32_t sb = shb + st * STAGE_BYTES;
        const int k0 = ck * BK;
#pragma unroll
        for (int it = 0; it < 4; it++) {
            int i = it * 256 + tid;
            int sp = i >> 9, rem = i & 511, r = rem >> 2, kq = rem & 3;
            cp16(sb + ((sp * BM + r) * PITCH + kq * 8) * 2,
                 Abase + (size_t)sp * kWelems + (size_t)(m0 + r) * kC + k0 + kq * 8);
        }
        {
            int r = tid >> 2, kq = tid & 3;
            cp16(sb + (A_ELEMS + r * PITCH + kq * 8) * 2,
                 g_sx + ((size_t)(t * kB + b) * kN + n0 + r) * kC + k0 + kq * 8);
        }
        asm volatile("cp.async.commit_group;");
    };

    // prologue: chunks 0,1 of t=0 into stages 0,1
    load_chunk(0, 0, 0);
    load_chunk(0, 1, 1);

    for (int t = 0; t < kT; t++) {
        float acch[2][4][4];
        uint32_t accl[2][4][2];
#pragma unroll
        for (int i = 0; i < 2; i++)
#pragma unroll
            for (int j = 0; j < 4; j++) {
#pragma unroll
                for (int q = 0; q < 4; q++) acch[i][j][q] = 0.f;
                accl[i][j][0] = 0u; accl[i][j][1] = 0u;
            }

        for (int cch = 0; cch < 12; cch++) {
            if (t == kT - 1 && cch == 11) {
                asm volatile("cp.async.wait_group 0;");
            } else {
                asm volatile("cp.async.wait_group 1;");
            }
            __syncthreads();
            if (cch <= 9) {
                load_chunk(t, cch + 2, (cch + 2) % 3);
            } else if (cch == 10 && t < kT - 1) {
                load_chunk(t + 1, 0, 0);
            }
            const uint32_t sb = shb + (cch % 3) * STAGE_BYTES;
#pragma unroll
            for (int ks = 0; ks < 2; ks++) {
                const int k0 = ks * 16;
                uint32_t bfr[2][4];
#pragma unroll
                for (int g = 0; g < 2; g++)
                    ldm_x4(bfr[g], sb + (A_ELEMS + (nw * 32 + g * 16 + ldrow) * PITCH + k0 + ldhalf * 8) * 2);
                // hi split: fp32 accumulate
                {
                    uint32_t afr[2][4];
#pragma unroll
                    for (int mi = 0; mi < 2; mi++)
                        ldm_x4(afr[mi], sb + ((0 * BM + mw * 32 + mi * 16 + ldrow) * PITCH + k0 + ldhalf * 8) * 2);
#pragma unroll
                    for (int mi = 0; mi < 2; mi++)
#pragma unroll
                        for (int nj = 0; nj < 4; nj++) {
                            int g = nj >> 1, w = nj & 1;
                            mma16816(acch[mi][nj], afr[mi], bfr[g][w], bfr[g][w + 2]);
                        }
                }
                // lo split: fp16 accumulate (2x rate; error scaled by 2^-12)
                {
                    uint32_t afr[2][4];
#pragma unroll
                    for (int mi = 0; mi < 2; mi++)
                        ldm_x4(afr[mi], sb + ((1 * BM + mw * 32 + mi * 16 + ldrow) * PITCH + k0 + ldhalf * 8) * 2);
#pragma unroll
                    for (int mi = 0; mi < 2; mi++)
#pragma unroll
                        for (int nj = 0; nj < 4; nj++) {
                            int g = nj >> 1, w = nj & 1;
                            mma16816h(accl[mi][nj], afr[mi], bfr[g][w], bfr[g][w + 2]);
                        }
                }
            }
        }

        // ---- BN + LIF epilogue for timestep t ----
#pragma unroll
        for (int mi = 0; mi < 2; mi++)
#pragma unroll
            for (int nj = 0; nj < 4; nj++) {
                float2 lo0 = __half22float2(*(__half2*)&accl[mi][nj][0]);  // q0, q1
                float2 lo1 = __half22float2(*(__half2*)&accl[mi][nj][1]);  // q2, q3
                float lov[4] = {lo0.x, lo0.y, lo1.x, lo1.y};
#pragma unroll
                for (int q = 0; q < 4; q++) {
                    const int half = q >> 1;
                    const int j = mi * 16 + nj * 4 + q;
                    float u = (acch[mi][nj][q] + lov[q] * kLoScale - mnv[mi][half]) * scv[mi][half] + bev[mi][half];
                    float vv = vsm[j * 256 + tid];
                    vv += (u - vv) * 0.5f;
                    float s = 0.f;
                    if (vv >= 0.5f) { s = 1.f; vv = 0.f; }
                    vsm[j * 256 + tid] = vv;

                    const int cl = mw * 32 + mi * 16 + half * 8 + gr;
                    const int n = nw * 32 + nj * 8 + gc + (q & 1);
                    if (p == 0) stg[n * QPITCH + cl] = __float2half(s);
                    else        stg[cl * KVP + n]   = __float2half(s);
                }
            }

        __syncthreads();
        if (p == 0) {
#pragma unroll
            for (int it = 0; it < 4; it++) {
                int i = it * 256 + tid;
                int n = i >> 4, w = i & 15;
                uint4 val = *(const uint4*)&stg[n * QPITCH + w * 8];
                *(uint4*)&g_qb[((size_t)((t * kB + b) * kN + n0 + n)) * kC + m0 + w * 8] = val;
            }
        } else {
            __half* dstb = (p == 1) ? g_kb : g_vb;
#pragma unroll
            for (int it = 0; it < 4; it++) {
                int i = it * 256 + tid;
                int cl = i >> 3, w = i & 7;
                uint4 val = *(const uint4*)&stg[cl * KVP + w * 8];
                *(uint4*)&dstb[((size_t)((t * kB + b) * kC + m0 + cl)) * kN + n0 + w * 8] = val;
            }
        }
        __syncthreads();
        if (t < kT - 1) load_chunk(t + 1, 1, 1);
    }
}

// ---------------------------------------------------------------------------
// kvsum: one warp per (t,b,c) row: sum_n k*v (binary fp16 -> exact).
// ---------------------------------------------------------------------------
__global__ void kvsum_kernel() {
    const int row = blockIdx.x * 8 + (threadIdx.x >> 5);
    const int lane = threadIdx.x & 31;
    const uint2* kp = (const uint2*)(g_kb + (size_t)row * kN);
    const uint2* vp = (const uint2*)(g_vb + (size_t)row * kN);
    float s = 0.f;
#pragma unroll
    for (int i = lane; i < kN / 4; i += 32) {
        uint2 kv4 = kp[i], vv4 = vp[i];
        __half2 p0 = __hmul2(*(__half2*)&kv4.x, *(__half2*)&vv4.x);
        __half2 p1 = __hmul2(*(__half2*)&kv4.y, *(__half2*)&vv4.y);
        float2 f0 = __half22float2(p0), f1 = __half22float2(p1);
        s += (f0.x + f0.y) + (f1.x + f1.y);
    }
#pragma unroll
    for (int o = 16; o; o >>= 1) s += __shfl_xor_sync(0xffffffffu, s, o);
    if (lane == 0) g_kvsum[row] = s;
}

// ---------------------------------------------------------------------------
// K4: talking heads + LIF on kv; kv spikes -> fp16.
// ---------------------------------------------------------------------------
__global__ void kv_kernel(const float* __restrict__ th_w) {
    __shared__ float th[64];
    if (threadIdx.x < 64) th[threadIdx.x] = th_w[threadIdx.x];
    __syncthreads();
    int d = threadIdx.x % 48;
    int b = threadIdx.x / 48;
    float v[8];
#pragma unroll
    for (int o = 0; o < 8; o++) v[o] = 0.0f;
#pragma unroll
    for (int t = 0; t < kT; t++) {
        float kvv[8];
#pragma unroll
        for (int h = 0; h < 8; h++)
            kvv[h] = g_kvsum[(t * kB + b) * kC + h * 48 + d];
#pragma unroll
        for (int o = 0; o < 8; o++) {
            float a = 0.0f;
#pragma unroll
            for (int h = 0; h < 8; h++) a += th[o * 8 + h] * kvv[h];
            v[o] += (a - v[o]) * 0.5f;
            float s = 0.f;
            if (v[o] >= 0.5f) { s = 1.f; v[o] = 0.f; }
            g_kvsh[(t * kB + b) * kC + o * 48 + d] = __float2half(s);
        }
    }
}

// ---------------------------------------------------------------------------
// PROJ GEMM: hi-split only (fp32 acc); B = q spikes * kvs (folded, exact).
// Epilogue: +bias, BN, +identity.
// ---------------------------------------------------------------------------
__global__ __launch_bounds__(256, 3) void gemm_proj_kernel(
    const float* __restrict__ pg, const float* __restrict__ pbe,
    const float* __restrict__ pm, const float* __restrict__ pva,
    const float* __restrict__ bias, const float* __restrict__ xres, float* __restrict__ outp)
{
    extern __shared__ __half sh[];
    const uint32_t shb = smem_u32(sh);

    const int tid = threadIdx.x, wid = tid >> 5, lane = tid & 31;
    const int bz = blockIdx.z, t = bz >> 3, b = bz & 7;
    const int m0 = blockIdx.y * BM, n0 = blockIdx.x * BN;

    const __half* Bimg = g_qb + (size_t)(t * kB + b) * kN * kC;
    const uint32_t* kvsp = (const uint32_t*)(g_kvsh + (t * kB + b) * kC);

    const int mw = wid >> 1, nw = wid & 1;

    float acch[2][4][4];
#pragma unroll
    for (int i = 0; i < 2; i++)
#pragma unroll
        for (int j = 0; j < 4; j++)
#pragma unroll
            for (int q = 0; q < 4; q++) acch[i][j][q] = 0.f;

    auto load_chunk = [&](int ck, int st) {
        const uint32_t sb = shb + st * PJSTAGE_BYTES;
        const int k0 = ck * BK;
#pragma unroll
        for (int it = 0; it < 2; it++) {
            int i = it * 256 + tid;
            int r = i >> 2, kq = i & 3;
            cp16(sb + (r * PITCH + kq * 8) * 2,
                 g_wp + (size_t)(m0 + r) * kC + k0 + kq * 8);
        }
        {
            int r = tid >> 2, kq = tid & 3;
            cp16(sb + (PJA_ELEMS + r * PITCH + kq * 8) * 2,
                 Bimg + (size_t)(n0 + r) * kC + k0 + kq * 8);
        }
        asm volatile("cp.async.commit_group;");
    };

    load_chunk(0, 0);
    const int ldrow = lane & 15, ldhalf = lane >> 4;

    for (int cch = 0; cch < kC / BK; cch++) {
        if (cch + 1 < kC / BK) {
            load_chunk(cch + 1, (cch + 1) & 1);
            asm volatile("cp.async.wait_group 1;");
        } else {
            asm volatile("cp.async.wait_group 0;");
        }
        __syncthreads();
        const uint32_t sb = shb + (cch & 1) * PJSTAGE_BYTES;
#pragma unroll
        for (int ks = 0; ks < 2; ks++) {
            const int k0 = ks * 16;
            uint32_t bfr[2][4];
#pragma unroll
            for (int g = 0; g < 2; g++)
                ldm_x4(bfr[g], sb + (PJA_ELEMS + (nw * 32 + g * 16 + ldrow) * PITCH + k0 + ldhalf * 8) * 2);
            {
                uint32_t p0 = kvsp[cch * 16 + ks * 8 + (lane & 3)];
                uint32_t p1 = kvsp[cch * 16 + ks * 8 + 4 + (lane & 3)];
#pragma unroll
                for (int g = 0; g < 2; g++) {
                    bfr[g][0] = hmul2u(bfr[g][0], p0);
                    bfr[g][1] = hmul2u(bfr[g][1], p0);
                    bfr[g][2] = hmul2u(bfr[g][2], p1);
                    bfr[g][3] = hmul2u(bfr[g][3], p1);
                }
            }
            uint32_t afr[2][4];
#pragma unroll
            for (int mi = 0; mi < 2; mi++)
                ldm_x4(afr[mi], sb + ((mw * 32 + mi * 16 + ldrow) * PITCH + k0 + ldhalf * 8) * 2);
#pragma unroll
            for (int mi = 0; mi < 2; mi++)
#pragma unroll
                for (int nj = 0; nj < 4; nj++) {
                    int g = nj >> 1, w = nj & 1;
                    mma16816(acch[mi][nj], afr[mi], bfr[g][w], bfr[g][w + 2]);
                }
        }
        __syncthreads();
    }

    const int gr = lane >> 2, gc = (lane & 3) * 2;
    const size_t imgoff = ((size_t)(t * kB + b) * kC) * kN;

#pragma unroll
    for (int mi = 0; mi < 2; mi++) {
#pragma unroll
        for (int half = 0; half < 2; half++) {
            const int c = m0 + mw * 32 + mi * 16 + gr + half * 8;
            const float sc = pg[c] / sqrtf(pva[c] + kEPS);
            const float mn = pm[c], be = pbe[c];
            const float bi = bias[c];
            size_t rowoff = imgoff + (size_t)c * kN;
            float* dst = outp + rowoff;
#pragma unroll
            for (int nj = 0; nj < 4; nj++) {
                const int n = n0 + nw * 32 + nj * 8 + gc;
                float v0 = acch[mi][nj][half * 2 + 0];
                float v1 = acch[mi][nj][half * 2 + 1];
                float2 xv = *(const float2*)(xres + rowoff + n);
                float2 o;
                o.x = ((v0 + bi) - mn) * sc + be + xv.x;
                o.y = ((v1 + bi) - mn) * sc + be + xv.y;
                *(float2*)(dst + n) = o;
            }
        }
    }
}

// ---------------------------------------------------------------------------
extern "C" void kernel_launch(void* const* d_in, const int* in_sizes, int n_in,
                              void* d_out, int out_size)
{
    const float* x   = (const float*)d_in[0];
    const float* qw  = (const float*)d_in[1];
    const float* kw  = (const float*)d_in[2];
    const float* vw  = (const float*)d_in[3];
    const float* thw = (const float*)d_in[4];
    const float* pw  = (const float*)d_in[5];
    const float* pb  = (const float*)d_in[6];
    const float* qg  = (const float*)d_in[7];
    const float* qbe = (const float*)d_in[8];
    const float* qm  = (const float*)d_in[9];
    const float* qva = (const float*)d_in[10];
    const float* kg  = (const float*)d_in[11];
    const float* kbe = (const float*)d_in[12];
    const float* km  = (const float*)d_in[13];
    const float* kva = (const float*)d_in[14];
    const float* vg  = (const float*)d_in[15];
    const float* vbe = (const float*)d_in[16];
    const float* vm  = (const float*)d_in[17];
    const float* vva = (const float*)d_in[18];
    const float* pg  = (const float*)d_in[19];
    const float* pbe = (const float*)d_in[20];
    const float* pm  = (const float*)d_in[21];
    const float* pva = (const float*)d_in[22];
    float* out = (float*)d_out;

    cudaFuncSetAttribute(fused_qkv_kernel, cudaFuncAttributeMaxDynamicSharedMemorySize, FSMEM);
    cudaFuncSetAttribute(gemm_proj_kernel, cudaFuncAttributeMaxDynamicSharedMemorySize, PJSMEM);

    split_w_kernel<<<(4 * kWelems + 255) / 256, 256>>>(qw, kw, vw, pw);

    lif_x_kernel<<<dim3(kN / 32, kC / 32, kB), 256>>>(x);

    fused_qkv_kernel<<<dim3(kN / BN, 9, kB), 256, FSMEM>>>(
        qg, qbe, qm, qva, kg, kbe, km, kva, vg, vbe, vm, vva);

    kvsum_kernel<<<kT * kB * kC / 8, 256>>>();

    kv_kernel<<<1, 384>>>(thw);

    gemm_proj_kernel<<<dim3(kN / BN, kC / BM, kT * kB), 256, PJSMEM>>>(
        pg, pbe, pm, pva, pb, x, out);
}

// round 15
// speedup vs baseline: 3.3491x; 1.0313x over previous
#include <cuda_runtime.h>
#include <cuda_fp16.h>
#include <cstdint>
#include <math.h>

constexpr int kT = 4, kB = 8, kC = 384, kN = 1024;
constexpr int kBCN  = kB * kC * kN;
constexpr int kTBCN = kT * kBCN;
constexpr float kEPS = 1e-5f;
constexpr int kWelems = kC * kC;            // 147456
constexpr float kLoScale = 1.0f / 4096.0f;

// ---------------- device scratch ----------------
__device__ __half g_wqkv[6 * kWelems];      // [branch*2+split][m][k]  (hi, lo*4096)
__device__ __half g_wp[2 * kWelems];        // [split][m][k] (proj uses hi only)
__device__ __half g_sx[kTBCN];              // input spikes  [t][b][n][c]
__device__ __half g_qb[kTBCN];              // q spikes      [t][b][n][c]
__device__ uint32_t g_kbm[kT * kB * kC * (kN / 32)];  // k spike bitmask [t][b][c][n/32]
__device__ uint32_t g_vbm[kT * kB * kC * (kN / 32)];  // v spike bitmask
__device__ float g_kvsum[kT * kB * kC];
__device__ __half g_kvsh[kT * kB * kC];     // kv spikes (fp16)

// ---------------- helpers ----------------
__device__ __forceinline__ uint32_t smem_u32(const void* p) {
    uint32_t a;
    asm("{ .reg .u64 t; cvta.to.shared.u64 t, %1; cvt.u32.u64 %0, t; }" : "=r"(a) : "l"(p));
    return a;
}
__device__ __forceinline__ void cp16(uint32_t dst, const void* src) {
    asm volatile("cp.async.cg.shared.global [%0], [%1], 16;" :: "r"(dst), "l"(src));
}
__device__ __forceinline__ void ldm_x4(uint32_t* r, uint32_t addr) {
    asm volatile("ldmatrix.sync.aligned.m8n8.x4.shared.b16 {%0,%1,%2,%3}, [%4];"
                 : "=r"(r[0]), "=r"(r[1]), "=r"(r[2]), "=r"(r[3]) : "r"(addr));
}
__device__ __forceinline__ void mma16816(float* c, const uint32_t* a, uint32_t b0, uint32_t b1) {
    asm volatile("mma.sync.aligned.m16n8k16.row.col.f32.f16.f16.f32 "
                 "{%0,%1,%2,%3}, {%4,%5,%6,%7}, {%8,%9}, {%0,%1,%2,%3};"
                 : "+f"(c[0]), "+f"(c[1]), "+f"(c[2]), "+f"(c[3])
                 : "r"(a[0]), "r"(a[1]), "r"(a[2]), "r"(a[3]), "r"(b0), "r"(b1));
}
// fp16-accumulate variant (2 packed half2 accumulator regs)
__device__ __forceinline__ void mma16816h(uint32_t* c, const uint32_t* a, uint32_t b0, uint32_t b1) {
    asm volatile("mma.sync.aligned.m16n8k16.row.col.f16.f16.f16.f16 "
                 "{%0,%1}, {%2,%3,%4,%5}, {%6,%7}, {%0,%1};"
                 : "+r"(c[0]), "+r"(c[1])
                 : "r"(a[0]), "r"(a[1]), "r"(a[2]), "r"(a[3]), "r"(b0), "r"(b1));
}
__device__ __forceinline__ uint32_t hmul2u(uint32_t a, uint32_t b) {
    __half2 r = __hmul2(*(__half2*)&a, *(__half2*)&b);
    return *(uint32_t*)&r;
}

// GEMM tiling: 128(M) x 64(N) x 32(K), 8 warps (4m x 2n), dual-split accumulation.
constexpr int BM = 128, BN = 64, BK = 32;
constexpr int PITCH = 40;                        // half elems per smem row (80B)
constexpr int A_ELEMS = 2 * BM * PITCH;          // 10240 (2 splits)
constexpr int B_ELEMS = BN * PITCH;              // 2560
constexpr int STAGE_ELEMS = A_ELEMS + B_ELEMS;   // 12800
constexpr int STAGE_BYTES = STAGE_ELEMS * 2;     // 25600
// fused kernel smem: 3 stages + LIF-state (256 threads x 32 floats)
constexpr int VST_OFF  = 3 * STAGE_BYTES;        // 76800
constexpr int FSMEM    = VST_OFF + 256 * 32 * 4; // 109568
// spike staging aliases stage 1 (free during epilogue); pitches in halves
constexpr int QPITCH = 136;
constexpr int KVP    = 72;

// proj kernel: 2 stages, hi split only
constexpr int PJA_ELEMS = BM * PITCH;                 // 5120
constexpr int PJSTAGE_ELEMS = PJA_ELEMS + B_ELEMS;    // 7680
constexpr int PJSTAGE_BYTES = PJSTAGE_ELEMS * 2;      // 15360
constexpr int PJSMEM = 2 * PJSTAGE_BYTES;             // 30720

// ---------------------------------------------------------------------------
// K0: split fp32 weights into (hi, lo*4096) fp16 pair.
// ---------------------------------------------------------------------------
__global__ void split_w_kernel(const float* __restrict__ qw, const float* __restrict__ kw,
                               const float* __restrict__ vw, const float* __restrict__ pw) {
    int idx = blockIdx.x * 256 + threadIdx.x;
    if (idx >= 4 * kWelems) return;
    int mat = idx / kWelems;
    int e = idx - mat * kWelems;
    const float* src = (mat == 0) ? qw : (mat == 1) ? kw : (mat == 2) ? vw : pw;
    float w = src[e];
    __half h = __float2half_rn(w);
    __half l = __float2half_rn((w - __half2float(h)) * 4096.0f);
    if (mat < 3) {
        g_wqkv[(mat * 2 + 0) * kWelems + e] = h;
        g_wqkv[(mat * 2 + 1) * kWelems + e] = l;
    } else {
        g_wp[0 * kWelems + e] = h;
        g_wp[1 * kWelems + e] = l;
    }
}

// ---------------------------------------------------------------------------
// K1: LIF on x [t][b][c][n] -> fp16 spikes transposed to [t][b][n][c].
// ---------------------------------------------------------------------------
__global__ void lif_x_kernel(const float* __restrict__ x) {
    __shared__ __half sm[32][36];
    const int lane = threadIdx.x & 31, wid = threadIdx.x >> 5;
    const int n0 = blockIdx.x * 32, c0 = blockIdx.y * 32, b = blockIdx.z;
    float v[4] = {0.f, 0.f, 0.f, 0.f};
    for (int t = 0; t < kT; t++) {
#pragma unroll
        for (int j = 0; j < 4; j++) {
            int c = c0 + wid * 4 + j;
            float xv = x[((size_t)((t * kB + b) * kC + c)) * kN + n0 + lane];
            v[j] += (xv - v[j]) * 0.5f;
            float s = 0.f;
            if (v[j] >= 0.5f) { s = 1.f; v[j] = 0.f; }
            sm[lane][wid * 4 + j] = __float2half(s);
        }
        __syncthreads();
        int nr = wid * 4 + (lane >> 3);
        int cw = (lane & 7) * 4;
        uint2 val = *(const uint2*)&sm[nr][cw];
        *(uint2*)&g_sx[((size_t)((t * kB + b) * kN + n0 + nr)) * kC + c0 + cw] = val;
        __syncthreads();
    }
}

// ---------------------------------------------------------------------------
// FUSED QKV: grid (16 ntiles, 9 = p*3+mtile, 8 b).
// 3-stage cp.async pipeline; hi split -> fp32-acc MMA, lo split -> fp16-acc
// MMA. BN+LIF epilogue; q spikes stored fp16 (MMA operand for proj), k/v
// spikes packed to BITMASKS (only consumer is the exact popcount kvsum).
// ---------------------------------------------------------------------------
__global__ __launch_bounds__(256, 2) void fused_qkv_kernel(
    const float* __restrict__ qg, const float* __restrict__ qbe, const float* __restrict__ qm, const float* __restrict__ qva,
    const float* __restrict__ kg, const float* __restrict__ kbe, const float* __restrict__ km, const float* __restrict__ kva,
    const float* __restrict__ vg, const float* __restrict__ vbe, const float* __restrict__ vm, const float* __restrict__ vva)
{
    extern __shared__ char dynsm[];
    const uint32_t shb = smem_u32(dynsm);
    float* vsm = (float*)(dynsm + VST_OFF);
    __half* stg = (__half*)(dynsm + STAGE_BYTES);   // aliases stage 1

    const int tid = threadIdx.x, wid = tid >> 5, lane = tid & 31;
    const int b = blockIdx.z;
    const int yy = blockIdx.y;
    const int p = (yy >= 6) ? 2 : ((yy >= 3) ? 1 : 0);
    const int mtile = yy - p * 3;
    const int m0 = mtile * BM, n0 = blockIdx.x * BN;

    const __half* Abase = g_wqkv + (size_t)(p * 2) * kWelems;
    const int mw = wid >> 1, nw = wid & 1;
    const int gr = lane >> 2, gc = (lane & 3) * 2;
    const int ldrow = lane & 15, ldhalf = lane >> 4;

    const float *G, *Be, *Mn, *Va;
    if (p == 0)      { G = qg; Be = qbe; Mn = qm; Va = qva; }
    else if (p == 1) { G = kg; Be = kbe; Mn = km; Va = kva; }
    else             { G = vg; Be = vbe; Mn = vm; Va = vva; }
    float scv[2][2], mnv[2][2], bev[2][2];
#pragma unroll
    for (int mi = 0; mi < 2; mi++)
#pragma unroll
        for (int half = 0; half < 2; half++) {
            int cc = m0 + mw * 32 + mi * 16 + half * 8 + gr;
            scv[mi][half] = G[cc] / sqrtf(Va[cc] + kEPS);
            mnv[mi][half] = Mn[cc];
            bev[mi][half] = Be[cc];
        }

#pragma unroll
    for (int j = 0; j < 32; j++) vsm[j * 256 + tid] = 0.f;

    auto load_chunk = [&](int t, int ck, int st) {
        const uint32_t sb = shb + st * STAGE_BYTES;
        const int k0 = ck * BK;
#pragma unroll
        for (int it = 0; it < 4; it++) {
            int i = it * 256 + tid;
            int sp = i >> 9, rem = i & 511, r = rem >> 2, kq = rem & 3;
            cp16(sb + ((sp * BM + r) * PITCH + kq * 8) * 2,
                 Abase + (size_t)sp * kWelems + (size_t)(m0 + r) * kC + k0 + kq * 8);
        }
        {
            int r = tid >> 2, kq = tid & 3;
            cp16(sb + (A_ELEMS + r * PITCH + kq * 8) * 2,
                 g_sx + ((size_t)(t * kB + b) * kN + n0 + r) * kC + k0 + kq * 8);
        }
        asm volatile("cp.async.commit_group;");
    };

    // prologue: chunks 0,1 of t=0 into stages 0,1
    load_chunk(0, 0, 0);
    load_chunk(0, 1, 1);

    for (int t = 0; t < kT; t++) {
        float acch[2][4][4];
        uint32_t accl[2][4][2];
#pragma unroll
        for (int i = 0; i < 2; i++)
#pragma unroll
            for (int j = 0; j < 4; j++) {
#pragma unroll
                for (int q = 0; q < 4; q++) acch[i][j][q] = 0.f;
                accl[i][j][0] = 0u; accl[i][j][1] = 0u;
            }

        for (int cch = 0; cch < 12; cch++) {
            if (t == kT - 1 && cch == 11) {
                asm volatile("cp.async.wait_group 0;");
            } else {
                asm volatile("cp.async.wait_group 1;");
            }
            __syncthreads();
            if (cch <= 9) {
                load_chunk(t, cch + 2, (cch + 2) % 3);
            } else if (cch == 10 && t < kT - 1) {
                load_chunk(t + 1, 0, 0);
            }
            const uint32_t sb = shb + (cch % 3) * STAGE_BYTES;
#pragma unroll
            for (int ks = 0; ks < 2; ks++) {
                const int k0 = ks * 16;
                uint32_t bfr[2][4];
#pragma unroll
                for (int g = 0; g < 2; g++)
                    ldm_x4(bfr[g], sb + (A_ELEMS + (nw * 32 + g * 16 + ldrow) * PITCH + k0 + ldhalf * 8) * 2);
                // hi split: fp32 accumulate
                {
                    uint32_t afr[2][4];
#pragma unroll
                    for (int mi = 0; mi < 2; mi++)
                        ldm_x4(afr[mi], sb + ((0 * BM + mw * 32 + mi * 16 + ldrow) * PITCH + k0 + ldhalf * 8) * 2);
#pragma unroll
                    for (int mi = 0; mi < 2; mi++)
#pragma unroll
                        for (int nj = 0; nj < 4; nj++) {
                            int g = nj >> 1, w = nj & 1;
                            mma16816(acch[mi][nj], afr[mi], bfr[g][w], bfr[g][w + 2]);
                        }
                }
                // lo split: fp16 accumulate (2x rate; error scaled by 2^-12)
                {
                    uint32_t afr[2][4];
#pragma unroll
                    for (int mi = 0; mi < 2; mi++)
                        ldm_x4(afr[mi], sb + ((1 * BM + mw * 32 + mi * 16 + ldrow) * PITCH + k0 + ldhalf * 8) * 2);
#pragma unroll
                    for (int mi = 0; mi < 2; mi++)
#pragma unroll
                        for (int nj = 0; nj < 4; nj++) {
                            int g = nj >> 1, w = nj & 1;
                            mma16816h(accl[mi][nj], afr[mi], bfr[g][w], bfr[g][w + 2]);
                        }
                }
            }
        }

        // ---- BN + LIF epilogue for timestep t ----
#pragma unroll
        for (int mi = 0; mi < 2; mi++)
#pragma unroll
            for (int nj = 0; nj < 4; nj++) {
                float2 lo0 = __half22float2(*(__half2*)&accl[mi][nj][0]);
                float2 lo1 = __half22float2(*(__half2*)&accl[mi][nj][1]);
                float lov[4] = {lo0.x, lo0.y, lo1.x, lo1.y};
#pragma unroll
                for (int q = 0; q < 4; q++) {
                    const int half = q >> 1;
                    const int j = mi * 16 + nj * 4 + q;
                    float u = (acch[mi][nj][q] + lov[q] * kLoScale - mnv[mi][half]) * scv[mi][half] + bev[mi][half];
                    float vv = vsm[j * 256 + tid];
                    vv += (u - vv) * 0.5f;
                    float s = 0.f;
                    if (vv >= 0.5f) { s = 1.f; vv = 0.f; }
                    vsm[j * 256 + tid] = vv;

                    const int cl = mw * 32 + mi * 16 + half * 8 + gr;
                    const int n = nw * 32 + nj * 8 + gc + (q & 1);
                    if (p == 0) stg[n * QPITCH + cl] = __float2half(s);
                    else        stg[cl * KVP + n]   = __float2half(s);
                }
            }

        __syncthreads();
        if (p == 0) {
#pragma unroll
            for (int it = 0; it < 4; it++) {
                int i = it * 256 + tid;
                int n = i >> 4, w = i & 15;
                uint4 val = *(const uint4*)&stg[n * QPITCH + w * 8];
                *(uint4*)&g_qb[((size_t)((t * kB + b) * kN + n0 + n)) * kC + m0 + w * 8] = val;
            }
        } else {
            // pack k/v spikes into bitmasks: 128 rows x 64 n-bits = 2 uint32/row
            const int cl = tid >> 1, h = tid & 1;
            const uint16_t* rp = (const uint16_t*)stg + cl * KVP + h * 32;
            uint32_t m = 0;
#pragma unroll
            for (int jj = 0; jj < 32; jj += 8) {
                uint4 v4 = *(const uint4*)(rp + jj);
                uint32_t w0 = v4.x, w1 = v4.y, w2 = v4.z, w3 = v4.w;
                if (w0 & 0xFFFFu) m |= 1u << (jj + 0);
                if (w0 >> 16)     m |= 1u << (jj + 1);
                if (w1 & 0xFFFFu) m |= 1u << (jj + 2);
                if (w1 >> 16)     m |= 1u << (jj + 3);
                if (w2 & 0xFFFFu) m |= 1u << (jj + 4);
                if (w2 >> 16)     m |= 1u << (jj + 5);
                if (w3 & 0xFFFFu) m |= 1u << (jj + 6);
                if (w3 >> 16)     m |= 1u << (jj + 7);
            }
            uint32_t* dstb = (p == 1) ? g_kbm : g_vbm;
            dstb[((size_t)((t * kB + b) * kC + m0 + cl)) * (kN / 32) + (n0 >> 5) + h] = m;
        }
        __syncthreads();
        if (t < kT - 1) load_chunk(t + 1, 1, 1);
    }
}

// ---------------------------------------------------------------------------
// kvsum: one warp per (t,b,c) row; lane l owns bits [l*32, l*32+32):
// popcount(k & v) + warp reduce. Exact integer.
// ---------------------------------------------------------------------------
__global__ void kvsum_kernel() {
    const int row = blockIdx.x * 8 + (threadIdx.x >> 5);
    const int lane = threadIdx.x & 31;
    uint32_t kw = g_kbm[(size_t)row * 32 + lane];
    uint32_t vw = g_vbm[(size_t)row * 32 + lane];
    int s = __popc(kw & vw);
#pragma unroll
    for (int o = 16; o; o >>= 1) s += __shfl_xor_sync(0xffffffffu, s, o);
    if (lane == 0) g_kvsum[row] = (float)s;
}

// ---------------------------------------------------------------------------
// K4: talking heads + LIF on kv; kv spikes -> fp16.
// ---------------------------------------------------------------------------
__global__ void kv_kernel(const float* __restrict__ th_w) {
    __shared__ float th[64];
    if (threadIdx.x < 64) th[threadIdx.x] = th_w[threadIdx.x];
    __syncthreads();
    int d = threadIdx.x % 48;
    int b = threadIdx.x / 48;
    float v[8];
#pragma unroll
    for (int o = 0; o < 8; o++) v[o] = 0.0f;
#pragma unroll
    for (int t = 0; t < kT; t++) {
        float kvv[8];
#pragma unroll
        for (int h = 0; h < 8; h++)
            kvv[h] = g_kvsum[(t * kB + b) * kC + h * 48 + d];
#pragma unroll
        for (int o = 0; o < 8; o++) {
            float a = 0.0f;
#pragma unroll
            for (int h = 0; h < 8; h++) a += th[o * 8 + h] * kvv[h];
            v[o] += (a - v[o]) * 0.5f;
            float s = 0.f;
            if (v[o] >= 0.5f) { s = 1.f; v[o] = 0.f; }
            g_kvsh[(t * kB + b) * kC + o * 48 + d] = __float2half(s);
        }
    }
}

// ---------------------------------------------------------------------------
// PROJ GEMM: hi-split only (fp32 acc); B = q spikes * kvs (folded, exact).
// Epilogue: +bias, BN, +identity.
// ---------------------------------------------------------------------------
__global__ __launch_bounds__(256, 3) void gemm_proj_kernel(
    const float* __restrict__ pg, const float* __restrict__ pbe,
    const float* __restrict__ pm, const float* __restrict__ pva,
    const float* __restrict__ bias, const float* __restrict__ xres, float* __restrict__ outp)
{
    extern __shared__ __half sh[];
    const uint32_t shb = smem_u32(sh);

    const int tid = threadIdx.x, wid = tid >> 5, lane = tid & 31;
    const int bz = blockIdx.z, t = bz >> 3, b = bz & 7;
    const int m0 = blockIdx.y * BM, n0 = blockIdx.x * BN;

    const __half* Bimg = g_qb + (size_t)(t * kB + b) * kN * kC;
    const uint32_t* kvsp = (const uint32_t*)(g_kvsh + (t * kB + b) * kC);

    const int mw = wid >> 1, nw = wid & 1;

    float acch[2][4][4];
#pragma unroll
    for (int i = 0; i < 2; i++)
#pragma unroll
        for (int j = 0; j < 4; j++)
#pragma unroll
            for (int q = 0; q < 4; q++) acch[i][j][q] = 0.f;

    auto load_chunk = [&](int ck, int st) {
        const uint32_t sb = shb + st * PJSTAGE_BYTES;
        const int k0 = ck * BK;
#pragma unroll
        for (int it = 0; it < 2; it++) {
            int i = it * 256 + tid;
            int r = i >> 2, kq = i & 3;
            cp16(sb + (r * PITCH + kq * 8) * 2,
                 g_wp + (size_t)(m0 + r) * kC + k0 + kq * 8);
        }
        {
            int r = tid >> 2, kq = tid & 3;
            cp16(sb + (PJA_ELEMS + r * PITCH + kq * 8) * 2,
                 Bimg + (size_t)(n0 + r) * kC + k0 + kq * 8);
        }
        asm volatile("cp.async.commit_group;");
    };

    load_chunk(0, 0);
    const int ldrow = lane & 15, ldhalf = lane >> 4;

    for (int cch = 0; cch < kC / BK; cch++) {
        if (cch + 1 < kC / BK) {
            load_chunk(cch + 1, (cch + 1) & 1);
            asm volatile("cp.async.wait_group 1;");
        } else {
            asm volatile("cp.async.wait_group 0;");
        }
        __syncthreads();
        const uint32_t sb = shb + (cch & 1) * PJSTAGE_BYTES;
#pragma unroll
        for (int ks = 0; ks < 2; ks++) {
            const int k0 = ks * 16;
            uint32_t bfr[2][4];
#pragma unroll
            for (int g = 0; g < 2; g++)
                ldm_x4(bfr[g], sb + (PJA_ELEMS + (nw * 32 + g * 16 + ldrow) * PITCH + k0 + ldhalf * 8) * 2);
            {
                uint32_t p0 = kvsp[cch * 16 + ks * 8 + (lane & 3)];
                uint32_t p1 = kvsp[cch * 16 + ks * 8 + 4 + (lane & 3)];
#pragma unroll
                for (int g = 0; g < 2; g++) {
                    bfr[g][0] = hmul2u(bfr[g][0], p0);
                    bfr[g][1] = hmul2u(bfr[g][1], p0);
                    bfr[g][2] = hmul2u(bfr[g][2], p1);
                    bfr[g][3] = hmul2u(bfr[g][3], p1);
                }
            }
            uint32_t afr[2][4];
#pragma unroll
            for (int mi = 0; mi < 2; mi++)
                ldm_x4(afr[mi], sb + ((mw * 32 + mi * 16 + ldrow) * PITCH + k0 + ldhalf * 8) * 2);
#pragma unroll
            for (int mi = 0; mi < 2; mi++)
#pragma unroll
                for (int nj = 0; nj < 4; nj++) {
                    int g = nj >> 1, w = nj & 1;
                    mma16816(acch[mi][nj], afr[mi], bfr[g][w], bfr[g][w + 2]);
                }
        }
        __syncthreads();
    }

    const int gr = lane >> 2, gc = (lane & 3) * 2;
    const size_t imgoff = ((size_t)(t * kB + b) * kC) * kN;

#pragma unroll
    for (int mi = 0; mi < 2; mi++) {
#pragma unroll
        for (int half = 0; half < 2; half++) {
            const int c = m0 + mw * 32 + mi * 16 + gr + half * 8;
            const float sc = pg[c] / sqrtf(pva[c] + kEPS);
            const float mn = pm[c], be = pbe[c];
            const float bi = bias[c];
            size_t rowoff = imgoff + (size_t)c * kN;
            float* dst = outp + rowoff;
#pragma unroll
            for (int nj = 0; nj < 4; nj++) {
                const int n = n0 + nw * 32 + nj * 8 + gc;
                float v0 = acch[mi][nj][half * 2 + 0];
                float v1 = acch[mi][nj][half * 2 + 1];
                float2 xv = *(const float2*)(xres + rowoff + n);
                float2 o;
                o.x = ((v0 + bi) - mn) * sc + be + xv.x;
                o.y = ((v1 + bi) - mn) * sc + be + xv.y;
                *(float2*)(dst + n) = o;
            }
        }
    }
}

// ---------------------------------------------------------------------------
extern "C" void kernel_launch(void* const* d_in, const int* in_sizes, int n_in,
                              void* d_out, int out_size)
{
    const float* x   = (const float*)d_in[0];
    const float* qw  = (const float*)d_in[1];
    const float* kw  = (const float*)d_in[2];
    const float* vw  = (const float*)d_in[3];
    const float* thw = (const float*)d_in[4];
    const float* pw  = (const float*)d_in[5];
    const float* pb  = (const float*)d_in[6];
    const float* qg  = (const float*)d_in[7];
    const float* qbe = (const float*)d_in[8];
    const float* qm  = (const float*)d_in[9];
    const float* qva = (const float*)d_in[10];
    const float* kg  = (const float*)d_in[11];
    const float* kbe = (const float*)d_in[12];
    const float* km  = (const float*)d_in[13];
    const float* kva = (const float*)d_in[14];
    const float* vg  = (const float*)d_in[15];
    const float* vbe = (const float*)d_in[16];
    const float* vm  = (const float*)d_in[17];
    const float* vva = (const float*)d_in[18];
    const float* pg  = (const float*)d_in[19];
    const float* pbe = (const float*)d_in[20];
    const float* pm  = (const float*)d_in[21];
    const float* pva = (const float*)d_in[22];
    float* out = (float*)d_out;

    cudaFuncSetAttribute(fused_qkv_kernel, cudaFuncAttributeMaxDynamicSharedMemorySize, FSMEM);
    cudaFuncSetAttribute(gemm_proj_kernel, cudaFuncAttributeMaxDynamicSharedMemorySize, PJSMEM);

    split_w_kernel<<<(4 * kWelems + 255) / 256, 256>>>(qw, kw, vw, pw);

    lif_x_kernel<<<dim3(kN / 32, kC / 32, kB), 256>>>(x);

    fused_qkv_kernel<<<dim3(kN / BN, 9, kB), 256, FSMEM>>>(
        qg, qbe, qm, qva, kg, kbe, km, kva, vg, vbe, vm, vva);

    kvsum_kernel<<<kT * kB * kC / 8, 256>>>();

    kv_kernel<<<1, 384>>>(thw);

    gemm_proj_kernel<<<dim3(kN / BN, kC / BM, kT * kB), 256, PJSMEM>>>(
        pg, pbe, pm, pva, pb, x, out);
}

// round 16
// speedup vs baseline: 3.4403x; 1.0272x over previous
#include <cuda_runtime.h>
#include <cuda_fp16.h>
#include <cstdint>
#include <math.h>

constexpr int kT = 4, kB = 8, kC = 384, kN = 1024;
constexpr int kBCN  = kB * kC * kN;
constexpr int kTBCN = kT * kBCN;
constexpr float kEPS = 1e-5f;
constexpr int kWelems = kC * kC;            // 147456
constexpr float kLoScale = 1.0f / 4096.0f;

// ---------------- device scratch ----------------
__device__ __half g_wqkv[6 * kWelems];      // [branch*2+split][m][k]  (hi, lo*4096)
__device__ __half g_wp[2 * kWelems];        // [split][m][k] (proj uses hi only)
__device__ __half g_sx[kTBCN];              // input spikes  [t][b][n][c]
__device__ __half g_qb[kTBCN];              // q spikes      [t][b][n][c]
__device__ uint32_t g_kbm[kT * kB * kC * (kN / 32)];  // k spike bitmask [t][b][c][n/32]
__device__ uint32_t g_vbm[kT * kB * kC * (kN / 32)];  // v spike bitmask
__device__ float g_kvsum[kT * kB * kC];
__device__ __half g_kvsh[kT * kB * kC];     // kv spikes (fp16)

// ---------------- helpers ----------------
__device__ __forceinline__ uint32_t smem_u32(const void* p) {
    uint32_t a;
    asm("{ .reg .u64 t; cvta.to.shared.u64 t, %1; cvt.u32.u64 %0, t; }" : "=r"(a) : "l"(p));
    return a;
}
__device__ __forceinline__ void cp16(uint32_t dst, const void* src) {
    asm volatile("cp.async.cg.shared.global [%0], [%1], 16;" :: "r"(dst), "l"(src));
}
__device__ __forceinline__ void ldm_x4(uint32_t* r, uint32_t addr) {
    asm volatile("ldmatrix.sync.aligned.m8n8.x4.shared.b16 {%0,%1,%2,%3}, [%4];"
                 : "=r"(r[0]), "=r"(r[1]), "=r"(r[2]), "=r"(r[3]) : "r"(addr));
}
__device__ __forceinline__ void mma16816(float* c, const uint32_t* a, uint32_t b0, uint32_t b1) {
    asm volatile("mma.sync.aligned.m16n8k16.row.col.f32.f16.f16.f32 "
                 "{%0,%1,%2,%3}, {%4,%5,%6,%7}, {%8,%9}, {%0,%1,%2,%3};"
                 : "+f"(c[0]), "+f"(c[1]), "+f"(c[2]), "+f"(c[3])
                 : "r"(a[0]), "r"(a[1]), "r"(a[2]), "r"(a[3]), "r"(b0), "r"(b1));
}
// fp16-accumulate variant (2 packed half2 accumulator regs)
__device__ __forceinline__ void mma16816h(uint32_t* c, const uint32_t* a, uint32_t b0, uint32_t b1) {
    asm volatile("mma.sync.aligned.m16n8k16.row.col.f16.f16.f16.f16 "
                 "{%0,%1}, {%2,%3,%4,%5}, {%6,%7}, {%0,%1};"
                 : "+r"(c[0]), "+r"(c[1])
                 : "r"(a[0]), "r"(a[1]), "r"(a[2]), "r"(a[3]), "r"(b0), "r"(b1));
}
__device__ __forceinline__ uint32_t hmul2u(uint32_t a, uint32_t b) {
    __half2 r = __hmul2(*(__half2*)&a, *(__half2*)&b);
    return *(uint32_t*)&r;
}

// GEMM tiling: 128(M) x 64(N) x 32(K), 8 warps (4m x 2n).
constexpr int BM = 128, BN = 64, BK = 32;
constexpr int PITCH = 40;                        // half elems per smem row (80B)
constexpr int A_ELEMS = 2 * BM * PITCH;          // 10240 (2 splits)
constexpr int B_ELEMS = BN * PITCH;              // 2560
constexpr int STAGE_ELEMS = A_ELEMS + B_ELEMS;   // 12800
constexpr int STAGE_BYTES = STAGE_ELEMS * 2;     // 25600
constexpr int VST_OFF  = 3 * STAGE_BYTES;        // 76800
constexpr int FSMEM    = VST_OFF + 256 * 32 * 4; // 109568
constexpr int QPITCH = 136;
constexpr int KVP    = 72;

// proj kernel: 3 stages, hi split only
constexpr int PJA_ELEMS = BM * PITCH;                 // 5120
constexpr int PJSTAGE_ELEMS = PJA_ELEMS + B_ELEMS;    // 7680
constexpr int PJSTAGE_BYTES = PJSTAGE_ELEMS * 2;      // 15360
constexpr int PJSMEM = 3 * PJSTAGE_BYTES;             // 46080

// ---------------------------------------------------------------------------
// K1 (merged): z<8 -> LIF on x for batch z; z>=8 -> weight split blocks.
// ---------------------------------------------------------------------------
__global__ void lif_x_split_kernel(const float* __restrict__ x,
                                   const float* __restrict__ qw, const float* __restrict__ kw,
                                   const float* __restrict__ vw, const float* __restrict__ pw) {
    if (blockIdx.z >= kB) {
        // weight-split part: 2304 blocks cover 4*kWelems elements
        int bidx = (blockIdx.z - kB) * (gridDim.y * gridDim.x) + blockIdx.y * gridDim.x + blockIdx.x;
        int idx = bidx * 256 + threadIdx.x;
        if (idx >= 4 * kWelems) return;
        int mat = idx / kWelems;
        int e = idx - mat * kWelems;
        const float* src = (mat == 0) ? qw : (mat == 1) ? kw : (mat == 2) ? vw : pw;
        float w = src[e];
        __half h = __float2half_rn(w);
        __half l = __float2half_rn((w - __half2float(h)) * 4096.0f);
        if (mat < 3) {
            g_wqkv[(mat * 2 + 0) * kWelems + e] = h;
            g_wqkv[(mat * 2 + 1) * kWelems + e] = l;
        } else {
            g_wp[0 * kWelems + e] = h;
            g_wp[1 * kWelems + e] = l;
        }
        return;
    }
    __shared__ __half sm[32][36];
    const int lane = threadIdx.x & 31, wid = threadIdx.x >> 5;
    const int n0 = blockIdx.x * 32, c0 = blockIdx.y * 32, b = blockIdx.z;
    float v[4] = {0.f, 0.f, 0.f, 0.f};
    for (int t = 0; t < kT; t++) {
#pragma unroll
        for (int j = 0; j < 4; j++) {
            int c = c0 + wid * 4 + j;
            float xv = x[((size_t)((t * kB + b) * kC + c)) * kN + n0 + lane];
            v[j] += (xv - v[j]) * 0.5f;
            float s = 0.f;
            if (v[j] >= 0.5f) { s = 1.f; v[j] = 0.f; }
            sm[lane][wid * 4 + j] = __float2half(s);
        }
        __syncthreads();
        int nr = wid * 4 + (lane >> 3);
        int cw = (lane & 7) * 4;
        uint2 val = *(const uint2*)&sm[nr][cw];
        *(uint2*)&g_sx[((size_t)((t * kB + b) * kN + n0 + nr)) * kC + c0 + cw] = val;
        __syncthreads();
    }
}

// ---------------------------------------------------------------------------
// FUSED QKV (identical to R15): 3-stage pipeline, hi fp32-acc + lo fp16-acc,
// BN+LIF epilogue, q spikes fp16, k/v spikes bit-packed.
// ---------------------------------------------------------------------------
__global__ __launch_bounds__(256, 2) void fused_qkv_kernel(
    const float* __restrict__ qg, const float* __restrict__ qbe, const float* __restrict__ qm, const float* __restrict__ qva,
    const float* __restrict__ kg, const float* __restrict__ kbe, const float* __restrict__ km, const float* __restrict__ kva,
    const float* __restrict__ vg, const float* __restrict__ vbe, const float* __restrict__ vm, const float* __restrict__ vva)
{
    extern __shared__ char dynsm[];
    const uint32_t shb = smem_u32(dynsm);
    float* vsm = (float*)(dynsm + VST_OFF);
    __half* stg = (__half*)(dynsm + STAGE_BYTES);   // aliases stage 1

    const int tid = threadIdx.x, wid = tid >> 5, lane = tid & 31;
    const int b = blockIdx.z;
    const int yy = blockIdx.y;
    const int p = (yy >= 6) ? 2 : ((yy >= 3) ? 1 : 0);
    const int mtile = yy - p * 3;
    const int m0 = mtile * BM, n0 = blockIdx.x * BN;

    const __half* Abase = g_wqkv + (size_t)(p * 2) * kWelems;
    const int mw = wid >> 1, nw = wid & 1;
    const int gr = lane >> 2, gc = (lane & 3) * 2;
    const int ldrow = lane & 15, ldhalf = lane >> 4;

    const float *G, *Be, *Mn, *Va;
    if (p == 0)      { G = qg; Be = qbe; Mn = qm; Va = qva; }
    else if (p == 1) { G = kg; Be = kbe; Mn = km; Va = kva; }
    else             { G = vg; Be = vbe; Mn = vm; Va = vva; }
    float scv[2][2], mnv[2][2], bev[2][2];
#pragma unroll
    for (int mi = 0; mi < 2; mi++)
#pragma unroll
        for (int half = 0; half < 2; half++) {
            int cc = m0 + mw * 32 + mi * 16 + half * 8 + gr;
            scv[mi][half] = G[cc] / sqrtf(Va[cc] + kEPS);
            mnv[mi][half] = Mn[cc];
            bev[mi][half] = Be[cc];
        }

#pragma unroll
    for (int j = 0; j < 32; j++) vsm[j * 256 + tid] = 0.f;

    auto load_chunk = [&](int t, int ck, int st) {
        const uint32_t sb = shb + st * STAGE_BYTES;
        const int k0 = ck * BK;
#pragma unroll
        for (int it = 0; it < 4; it++) {
            int i = it * 256 + tid;
            int sp = i >> 9, rem = i & 511, r = rem >> 2, kq = rem & 3;
            cp16(sb + ((sp * BM + r) * PITCH + kq * 8) * 2,
                 Abase + (size_t)sp * kWelems + (size_t)(m0 + r) * kC + k0 + kq * 8);
        }
        {
            int r = tid >> 2, kq = tid & 3;
            cp16(sb + (A_ELEMS + r * PITCH + kq * 8) * 2,
                 g_sx + ((size_t)(t * kB + b) * kN + n0 + r) * kC + k0 + kq * 8);
        }
        asm volatile("cp.async.commit_group;");
    };

    load_chunk(0, 0, 0);
    load_chunk(0, 1, 1);

    for (int t = 0; t < kT; t++) {
        float acch[2][4][4];
        uint32_t accl[2][4][2];
#pragma unroll
        for (int i = 0; i < 2; i++)
#pragma unroll
            for (int j = 0; j < 4; j++) {
#pragma unroll
                for (int q = 0; q < 4; q++) acch[i][j][q] = 0.f;
                accl[i][j][0] = 0u; accl[i][j][1] = 0u;
            }

        for (int cch = 0; cch < 12; cch++) {
            if (t == kT - 1 && cch == 11) {
                asm volatile("cp.async.wait_group 0;");
            } else {
                asm volatile("cp.async.wait_group 1;");
            }
            __syncthreads();
            if (cch <= 9) {
                load_chunk(t, cch + 2, (cch + 2) % 3);
            } else if (cch == 10 && t < kT - 1) {
                load_chunk(t + 1, 0, 0);
            }
            const uint32_t sb = shb + (cch % 3) * STAGE_BYTES;
#pragma unroll
            for (int ks = 0; ks < 2; ks++) {
                const int k0 = ks * 16;
                uint32_t bfr[2][4];
#pragma unroll
                for (int g = 0; g < 2; g++)
                    ldm_x4(bfr[g], sb + (A_ELEMS + (nw * 32 + g * 16 + ldrow) * PITCH + k0 + ldhalf * 8) * 2);
                {
                    uint32_t afr[2][4];
#pragma unroll
                    for (int mi = 0; mi < 2; mi++)
                        ldm_x4(afr[mi], sb + ((0 * BM + mw * 32 + mi * 16 + ldrow) * PITCH + k0 + ldhalf * 8) * 2);
#pragma unroll
                    for (int mi = 0; mi < 2; mi++)
#pragma unroll
                        for (int nj = 0; nj < 4; nj++) {
                            int g = nj >> 1, w = nj & 1;
                            mma16816(acch[mi][nj], afr[mi], bfr[g][w], bfr[g][w + 2]);
                        }
                }
                {
                    uint32_t afr[2][4];
#pragma unroll
                    for (int mi = 0; mi < 2; mi++)
                        ldm_x4(afr[mi], sb + ((1 * BM + mw * 32 + mi * 16 + ldrow) * PITCH + k0 + ldhalf * 8) * 2);
#pragma unroll
                    for (int mi = 0; mi < 2; mi++)
#pragma unroll
                        for (int nj = 0; nj < 4; nj++) {
                            int g = nj >> 1, w = nj & 1;
                            mma16816h(accl[mi][nj], afr[mi], bfr[g][w], bfr[g][w + 2]);
                        }
                }
            }
        }

        // ---- BN + LIF epilogue for timestep t ----
#pragma unroll
        for (int mi = 0; mi < 2; mi++)
#pragma unroll
            for (int nj = 0; nj < 4; nj++) {
                float2 lo0 = __half22float2(*(__half2*)&accl[mi][nj][0]);
                float2 lo1 = __half22float2(*(__half2*)&accl[mi][nj][1]);
                float lov[4] = {lo0.x, lo0.y, lo1.x, lo1.y};
#pragma unroll
                for (int q = 0; q < 4; q++) {
                    const int half = q >> 1;
                    const int j = mi * 16 + nj * 4 + q;
                    float u = (acch[mi][nj][q] + lov[q] * kLoScale - mnv[mi][half]) * scv[mi][half] + bev[mi][half];
                    float vv = vsm[j * 256 + tid];
                    vv += (u - vv) * 0.5f;
                    float s = 0.f;
                    if (vv >= 0.5f) { s = 1.f; vv = 0.f; }
                    vsm[j * 256 + tid] = vv;

                    const int cl = mw * 32 + mi * 16 + half * 8 + gr;
                    const int n = nw * 32 + nj * 8 + gc + (q & 1);
                    if (p == 0) stg[n * QPITCH + cl] = __float2half(s);
                    else        stg[cl * KVP + n]   = __float2half(s);
                }
            }

        __syncthreads();
        if (p == 0) {
#pragma unroll
            for (int it = 0; it < 4; it++) {
                int i = it * 256 + tid;
                int n = i >> 4, w = i & 15;
                uint4 val = *(const uint4*)&stg[n * QPITCH + w * 8];
                *(uint4*)&g_qb[((size_t)((t * kB + b) * kN + n0 + n)) * kC + m0 + w * 8] = val;
            }
        } else {
            const int cl = tid >> 1, h = tid & 1;
            const uint16_t* rp = (const uint16_t*)stg + cl * KVP + h * 32;
            uint32_t m = 0;
#pragma unroll
            for (int jj = 0; jj < 32; jj += 8) {
                uint4 v4 = *(const uint4*)(rp + jj);
                uint32_t w0 = v4.x, w1 = v4.y, w2 = v4.z, w3 = v4.w;
                if (w0 & 0xFFFFu) m |= 1u << (jj + 0);
                if (w0 >> 16)     m |= 1u << (jj + 1);
                if (w1 & 0xFFFFu) m |= 1u << (jj + 2);
                if (w1 >> 16)     m |= 1u << (jj + 3);
                if (w2 & 0xFFFFu) m |= 1u << (jj + 4);
                if (w2 >> 16)     m |= 1u << (jj + 5);
                if (w3 & 0xFFFFu) m |= 1u << (jj + 6);
                if (w3 >> 16)     m |= 1u << (jj + 7);
            }
            uint32_t* dstb = (p == 1) ? g_kbm : g_vbm;
            dstb[((size_t)((t * kB + b) * kC + m0 + cl)) * (kN / 32) + (n0 >> 5) + h] = m;
        }
        __syncthreads();
        if (t < kT - 1) load_chunk(t + 1, 1, 1);
    }
}

// ---------------------------------------------------------------------------
// kvsum: warp per row, popcount(k & v), warp reduce. Exact.
// ---------------------------------------------------------------------------
__global__ void kvsum_kernel() {
    const int row = blockIdx.x * 8 + (threadIdx.x >> 5);
    const int lane = threadIdx.x & 31;
    uint32_t kw = g_kbm[(size_t)row * 32 + lane];
    uint32_t vw = g_vbm[(size_t)row * 32 + lane];
    int s = __popc(kw & vw);
#pragma unroll
    for (int o = 16; o; o >>= 1) s += __shfl_xor_sync(0xffffffffu, s, o);
    if (lane == 0) g_kvsum[row] = (float)s;
}

// ---------------------------------------------------------------------------
// K4: talking heads + LIF on kv; kv spikes -> fp16.
// ---------------------------------------------------------------------------
__global__ void kv_kernel(const float* __restrict__ th_w) {
    __shared__ float th[64];
    if (threadIdx.x < 64) th[threadIdx.x] = th_w[threadIdx.x];
    __syncthreads();
    int d = threadIdx.x % 48;
    int b = threadIdx.x / 48;
    float v[8];
#pragma unroll
    for (int o = 0; o < 8; o++) v[o] = 0.0f;
#pragma unroll
    for (int t = 0; t < kT; t++) {
        float kvv[8];
#pragma unroll
        for (int h = 0; h < 8; h++)
            kvv[h] = g_kvsum[(t * kB + b) * kC + h * 48 + d];
#pragma unroll
        for (int o = 0; o < 8; o++) {
            float a = 0.0f;
#pragma unroll
            for (int h = 0; h < 8; h++) a += th[o * 8 + h] * kvv[h];
            v[o] += (a - v[o]) * 0.5f;
            float s = 0.f;
            if (v[o] >= 0.5f) { s = 1.f; v[o] = 0.f; }
            g_kvsh[(t * kB + b) * kC + o * 48 + d] = __float2half(s);
        }
    }
}

// ---------------------------------------------------------------------------
// PROJ GEMM: 3-stage pipeline, ONE sync per chunk; hi split, fp32 acc;
// B = q spikes * kvs (folded, exact). Epilogue: +bias, BN, +identity.
// ---------------------------------------------------------------------------
__global__ __launch_bounds__(256, 3) void gemm_proj_kernel(
    const float* __restrict__ pg, const float* __restrict__ pbe,
    const float* __restrict__ pm, const float* __restrict__ pva,
    const float* __restrict__ bias, const float* __restrict__ xres, float* __restrict__ outp)
{
    extern __shared__ __half sh[];
    const uint32_t shb = smem_u32(sh);

    const int tid = threadIdx.x, wid = tid >> 5, lane = tid & 31;
    const int bz = blockIdx.z, t = bz >> 3, b = bz & 7;
    const int m0 = blockIdx.y * BM, n0 = blockIdx.x * BN;

    const __half* Bimg = g_qb + (size_t)(t * kB + b) * kN * kC;
    const uint32_t* kvsp = (const uint32_t*)(g_kvsh + (t * kB + b) * kC);

    const int mw = wid >> 1, nw = wid & 1;

    float acch[2][4][4];
#pragma unroll
    for (int i = 0; i < 2; i++)
#pragma unroll
        for (int j = 0; j < 4; j++)
#pragma unroll
            for (int q = 0; q < 4; q++) acch[i][j][q] = 0.f;

    auto load_chunk = [&](int ck, int st) {
        const uint32_t sb = shb + st * PJSTAGE_BYTES;
        const int k0 = ck * BK;
#pragma unroll
        for (int it = 0; it < 2; it++) {
            int i = it * 256 + tid;
            int r = i >> 2, kq = i & 3;
            cp16(sb + (r * PITCH + kq * 8) * 2,
                 g_wp + (size_t)(m0 + r) * kC + k0 + kq * 8);
        }
        {
            int r = tid >> 2, kq = tid & 3;
            cp16(sb + (PJA_ELEMS + r * PITCH + kq * 8) * 2,
                 Bimg + (size_t)(n0 + r) * kC + k0 + kq * 8);
        }
        asm volatile("cp.async.commit_group;");
    };

    load_chunk(0, 0);
    load_chunk(1, 1);
    const int ldrow = lane & 15, ldhalf = lane >> 4;

    for (int cch = 0; cch < 12; cch++) {
        if (cch == 11) {
            asm volatile("cp.async.wait_group 0;");
        } else {
            asm volatile("cp.async.wait_group 1;");
        }
        __syncthreads();
        if (cch <= 9) load_chunk(cch + 2, (cch + 2) % 3);
        const uint32_t sb = shb + (cch % 3) * PJSTAGE_BYTES;
#pragma unroll
        for (int ks = 0; ks < 2; ks++) {
            const int k0 = ks * 16;
            uint32_t bfr[2][4];
#pragma unroll
            for (int g = 0; g < 2; g++)
                ldm_x4(bfr[g], sb + (PJA_ELEMS + (nw * 32 + g * 16 + ldrow) * PITCH + k0 + ldhalf * 8) * 2);
            {
                uint32_t p0 = kvsp[cch * 16 + ks * 8 + (lane & 3)];
                uint32_t p1 = kvsp[cch * 16 + ks * 8 + 4 + (lane & 3)];
#pragma unroll
                for (int g = 0; g < 2; g++) {
                    bfr[g][0] = hmul2u(bfr[g][0], p0);
                    bfr[g][1] = hmul2u(bfr[g][1], p0);
                    bfr[g][2] = hmul2u(bfr[g][2], p1);
                    bfr[g][3] = hmul2u(bfr[g][3], p1);
                }
            }
            uint32_t afr[2][4];
#pragma unroll
            for (int mi = 0; mi < 2; mi++)
                ldm_x4(afr[mi], sb + ((mw * 32 + mi * 16 + ldrow) * PITCH + k0 + ldhalf * 8) * 2);
#pragma unroll
            for (int mi = 0; mi < 2; mi++)
#pragma unroll
                for (int nj = 0; nj < 4; nj++) {
                    int g = nj >> 1, w = nj & 1;
                    mma16816(acch[mi][nj], afr[mi], bfr[g][w], bfr[g][w + 2]);
                }
        }
    }

    const int gr = lane >> 2, gc = (lane & 3) * 2;
    const size_t imgoff = ((size_t)(t * kB + b) * kC) * kN;

#pragma unroll
    for (int mi = 0; mi < 2; mi++) {
#pragma unroll
        for (int half = 0; half < 2; half++) {
            const int c = m0 + mw * 32 + mi * 16 + gr + half * 8;
            const float sc = pg[c] / sqrtf(pva[c] + kEPS);
            const float mn = pm[c], be = pbe[c];
            const float bi = bias[c];
            size_t rowoff = imgoff + (size_t)c * kN;
            float* dst = outp + rowoff;
#pragma unroll
            for (int nj = 0; nj < 4; nj++) {
                const int n = n0 + nw * 32 + nj * 8 + gc;
                float v0 = acch[mi][nj][half * 2 + 0];
                float v1 = acch[mi][nj][half * 2 + 1];
                float2 xv = *(const float2*)(xres + rowoff + n);
                float2 o;
                o.x = ((v0 + bi) - mn) * sc + be + xv.x;
                o.y = ((v1 + bi) - mn) * sc + be + xv.y;
                *(float2*)(dst + n) = o;
            }
        }
    }
}

// ---------------------------------------------------------------------------
extern "C" void kernel_launch(void* const* d_in, const int* in_sizes, int n_in,
                              void* d_out, int out_size)
{
    const float* x   = (const float*)d_in[0];
    const float* qw  = (const float*)d_in[1];
    const float* kw  = (const float*)d_in[2];
    const float* vw  = (const float*)d_in[3];
    const float* thw = (const float*)d_in[4];
    const float* pw  = (const float*)d_in[5];
    const float* pb  = (const float*)d_in[6];
    const float* qg  = (const float*)d_in[7];
    const float* qbe = (const float*)d_in[8];
    const float* qm  = (const float*)d_in[9];
    const float* qva = (const float*)d_in[10];
    const float* kg  = (const float*)d_in[11];
    const float* kbe = (const float*)d_in[12];
    const float* km  = (const float*)d_in[13];
    const float* kva = (const float*)d_in[14];
    const float* vg  = (const float*)d_in[15];
    const float* vbe = (const float*)d_in[16];
    const float* vm  = (const float*)d_in[17];
    const float* vva = (const float*)d_in[18];
    const float* pg  = (const float*)d_in[19];
    const float* pbe = (const float*)d_in[20];
    const float* pm  = (const float*)d_in[21];
    const float* pva = (const float*)d_in[22];
    float* out = (float*)d_out;

    cudaFuncSetAttribute(fused_qkv_kernel, cudaFuncAttributeMaxDynamicSharedMemorySize, FSMEM);
    cudaFuncSetAttribute(gemm_proj_kernel, cudaFuncAttributeMaxDynamicSharedMemorySize, PJSMEM);

    // merged LIF(x) + weight-split: z<8 lif (32x12 tiles per b), z in [8,14) split
    lif_x_split_kernel<<<dim3(kN / 32, kC / 32, kB + 6), 256>>>(x, qw, kw, vw, pw);

    fused_qkv_kernel<<<dim3(kN / BN, 9, kB), 256, FSMEM>>>(
        qg, qbe, qm, qva, kg, kbe, km, kva, vg, vbe, vm, vva);

    kvsum_kernel<<<kT * kB * kC / 8, 256>>>();

    kv_kernel<<<1, 384>>>(thw);

    gemm_proj_kernel<<<dim3(kN / BN, kC / BM, kT * kB), 256, PJSMEM>>>(
        pg, pbe, pm, pva, pb, x, out);
}